// round 2
// baseline (speedup 1.0000x reference)
#include <cuda_runtime.h>

#define N_NODES 50000
#define N_EDGES 800000
#define N_GRAPHS 32
#define D 128
#define H 256

// ---------------- scratch (device globals: allocation-free kernel_launch) ----
__device__ float g_x[N_NODES * D];
__device__ float g_agg[N_NODES * D];
__device__ float g_d2[N_EDGES];

__device__ __forceinline__ float swishf(float v) {
    return v / (1.f + __expf(-v));
}

// ---------------- small utility kernels --------------------------------------
__global__ void zero_agg_kernel() {
    int i = blockIdx.x * blockDim.x + threadIdx.x;
    if (i < N_NODES * D) g_agg[i] = 0.f;
}

__global__ void zero_out_kernel(float* __restrict__ out) {
    if (threadIdx.x < N_GRAPHS) out[threadIdx.x] = 0.f;
}

__global__ void d2_kernel(const float* __restrict__ pos,
                          const float* __restrict__ shift,
                          const float* __restrict__ lat,
                          const int* __restrict__ ei,
                          const int* __restrict__ batch) {
    int e = blockIdx.x * blockDim.x + threadIdx.x;
    if (e >= N_EDGES) return;
    int s = ei[e];
    int d = ei[N_EDGES + e];
    int g = batch[s];
    const float* L = lat + g * 9;
    float sx = shift[e * 3 + 0], sy = shift[e * 3 + 1], sz = shift[e * 3 + 2];
    float vx = pos[d * 3 + 0] - pos[s * 3 + 0] + sx * L[0] + sy * L[3] + sz * L[6];
    float vy = pos[d * 3 + 1] - pos[s * 3 + 1] + sx * L[1] + sy * L[4] + sz * L[7];
    float vz = pos[d * 3 + 2] - pos[s * 3 + 2] + sx * L[2] + sy * L[5] + sz * L[8];
    g_d2[e] = vx * vx + vy * vy + vz * vz;
}

__global__ void embed_kernel(const float* __restrict__ embed,
                             const int* __restrict__ z) {
    int i = blockIdx.x * blockDim.x + threadIdx.x;
    if (i >= N_NODES * D) return;
    int n = i >> 7, c = i & 127;
    g_x[i] = embed[z[n] * D + c];
}

// ---------------- fused edge MLP + scatter-add --------------------------------
// block = 32 edges, 256 threads.
// GEMM1: m1[32,256] = swish(ein[32,257] @ W1 + b1)   (ein = [x[dst] | x[src] | d2])
// GEMM2: m2[32,128] = swish(m1 @ W2 + b2)            then atomicAdd into agg[dst].
// Thread tile GEMM1: 4 edges x 8 cols (cols {cg*4..+3, 128+cg*4..+3} -> conflict-free LDS.128)
// Thread tile GEMM2: 4 edges x 4 cols.
__global__ __launch_bounds__(256) void edge_kernel(
    const float* __restrict__ W1, const float* __restrict__ b1,
    const float* __restrict__ W2, const float* __restrict__ b2,
    const int* __restrict__ ei)
{
    extern __shared__ float sm[];
    float* s_in = sm;                       // [32][256]
    float* s_w  = sm + 8192;                // weight staging [32][256]
    float* s_d2 = sm + 16384;               // [32]
    int*   s_src = (int*)(sm + 16384 + 32); // [32]
    int*   s_dst = s_src + 32;              // [32]

    const int t  = threadIdx.x;
    const int e0 = blockIdx.x * 32;
    if (t < 32) {
        s_src[t] = ei[e0 + t];
        s_dst[t] = ei[N_EDGES + e0 + t];
        s_d2[t]  = g_d2[e0 + t];
    }
    __syncthreads();

    // gather ein: cols 0..127 = x[dst], 128..255 = x[src]
    #pragma unroll
    for (int i = t; i < 32 * 64; i += 256) {
        const int e = i >> 6, q = i & 63;
        const float4* p = (q < 32)
            ? ((const float4*)(g_x + (size_t)s_dst[e] * D) + q)
            : ((const float4*)(g_x + (size_t)s_src[e] * D) + (q - 32));
        ((float4*)(s_in + e * 256))[q] = *p;
    }

    const int eg = t >> 5;   // edge group 0..7 -> edges eg*4..+3
    const int cg = t & 31;   // col group   0..31

    float acc[4][8];
    #pragma unroll
    for (int i = 0; i < 4; i++)
        #pragma unroll
        for (int j = 0; j < 8; j++) acc[i][j] = 0.f;

    // ---- GEMM1 over K=256 (rows 0..255 of W1); d2 row (256) folded in epilogue
    for (int k0 = 0; k0 < 256; k0 += 32) {
        __syncthreads();
        #pragma unroll
        for (int i = t; i < 2048; i += 256)
            ((float4*)s_w)[i] = ((const float4*)W1)[k0 * 64 + i];
        __syncthreads();
        #pragma unroll
        for (int kk4 = 0; kk4 < 32; kk4 += 4) {
            float xs[4][4];
            #pragma unroll
            for (int i = 0; i < 4; i++) {
                float4 xv = *((const float4*)(s_in + (eg * 4 + i) * 256 + k0 + kk4));
                xs[i][0] = xv.x; xs[i][1] = xv.y; xs[i][2] = xv.z; xs[i][3] = xv.w;
            }
            #pragma unroll
            for (int u = 0; u < 4; u++) {
                const int kk = kk4 + u;
                float4 w0 = *((const float4*)(s_w + kk * 256 + cg * 4));
                float4 w1 = *((const float4*)(s_w + kk * 256 + 128 + cg * 4));
                #pragma unroll
                for (int i = 0; i < 4; i++) {
                    float xv = xs[i][u];
                    acc[i][0] = fmaf(xv, w0.x, acc[i][0]);
                    acc[i][1] = fmaf(xv, w0.y, acc[i][1]);
                    acc[i][2] = fmaf(xv, w0.z, acc[i][2]);
                    acc[i][3] = fmaf(xv, w0.w, acc[i][3]);
                    acc[i][4] = fmaf(xv, w1.x, acc[i][4]);
                    acc[i][5] = fmaf(xv, w1.y, acc[i][5]);
                    acc[i][6] = fmaf(xv, w1.z, acc[i][6]);
                    acc[i][7] = fmaf(xv, w1.w, acc[i][7]);
                }
            }
        }
    }

    // epilogue: + d2 * W1[256,:] + b1, swish, store m1 back into s_in
    float4 wd0 = *((const float4*)(W1 + 256 * 256 + cg * 4));
    float4 wd1 = *((const float4*)(W1 + 256 * 256 + 128 + cg * 4));
    float4 bb0 = *((const float4*)(b1 + cg * 4));
    float4 bb1 = *((const float4*)(b1 + 128 + cg * 4));

    __syncthreads();
    #pragma unroll
    for (int i = 0; i < 4; i++) {
        float dv = s_d2[eg * 4 + i];
        float4 r0, r1;
        r0.x = swishf(fmaf(dv, wd0.x, acc[i][0]) + bb0.x);
        r0.y = swishf(fmaf(dv, wd0.y, acc[i][1]) + bb0.y);
        r0.z = swishf(fmaf(dv, wd0.z, acc[i][2]) + bb0.z);
        r0.w = swishf(fmaf(dv, wd0.w, acc[i][3]) + bb0.w);
        r1.x = swishf(fmaf(dv, wd1.x, acc[i][4]) + bb1.x);
        r1.y = swishf(fmaf(dv, wd1.y, acc[i][5]) + bb1.y);
        r1.z = swishf(fmaf(dv, wd1.z, acc[i][6]) + bb1.z);
        r1.w = swishf(fmaf(dv, wd1.w, acc[i][7]) + bb1.w);
        *((float4*)(s_in + (eg * 4 + i) * 256 + cg * 4)) = r0;
        *((float4*)(s_in + (eg * 4 + i) * 256 + 128 + cg * 4)) = r1;
    }

    // ---- GEMM2: [32,256] @ [256,128]
    float a2[4][4];
    #pragma unroll
    for (int i = 0; i < 4; i++)
        #pragma unroll
        for (int j = 0; j < 4; j++) a2[i][j] = 0.f;

    for (int k0 = 0; k0 < 256; k0 += 32) {
        __syncthreads();
        #pragma unroll
        for (int i = t; i < 1024; i += 256)
            ((float4*)s_w)[i] = ((const float4*)W2)[k0 * 32 + i];
        __syncthreads();
        #pragma unroll
        for (int kk4 = 0; kk4 < 32; kk4 += 4) {
            float xs[4][4];
            #pragma unroll
            for (int i = 0; i < 4; i++) {
                float4 xv = *((const float4*)(s_in + (eg * 4 + i) * 256 + k0 + kk4));
                xs[i][0] = xv.x; xs[i][1] = xv.y; xs[i][2] = xv.z; xs[i][3] = xv.w;
            }
            #pragma unroll
            for (int u = 0; u < 4; u++) {
                const int kk = kk4 + u;
                float4 wv = *((const float4*)(s_w + kk * 128 + cg * 4));
                #pragma unroll
                for (int i = 0; i < 4; i++) {
                    float xv = xs[i][u];
                    a2[i][0] = fmaf(xv, wv.x, a2[i][0]);
                    a2[i][1] = fmaf(xv, wv.y, a2[i][1]);
                    a2[i][2] = fmaf(xv, wv.z, a2[i][2]);
                    a2[i][3] = fmaf(xv, wv.w, a2[i][3]);
                }
            }
        }
    }

    float4 bb = *((const float4*)(b2 + cg * 4));
    #pragma unroll
    for (int i = 0; i < 4; i++) {
        float* ap = g_agg + (size_t)s_dst[eg * 4 + i] * D + cg * 4;
        atomicAdd(ap + 0, swishf(a2[i][0] + bb.x));
        atomicAdd(ap + 1, swishf(a2[i][1] + bb.y));
        atomicAdd(ap + 2, swishf(a2[i][2] + bb.z));
        atomicAdd(ap + 3, swishf(a2[i][3] + bb.w));
    }
}

// ---------------- fused node MLP (residual) -----------------------------------
__global__ __launch_bounds__(256) void node_kernel(
    const float* __restrict__ W1, const float* __restrict__ b1,
    const float* __restrict__ W2, const float* __restrict__ b2)
{
    extern __shared__ float sm[];
    float* s_in = sm;        // [32][256]
    float* s_w  = sm + 8192; // staging

    const int t  = threadIdx.x;
    const int n0 = blockIdx.x * 32;

    // gather hin = [x[n] | agg[n]]
    #pragma unroll
    for (int i = t; i < 32 * 64; i += 256) {
        const int r = i >> 6, q = i & 63;
        int n = n0 + r; if (n >= N_NODES) n = N_NODES - 1;
        ((float4*)(s_in + r * 256))[q] = (q < 32)
            ? ((const float4*)(g_x + (size_t)n * D))[q]
            : ((const float4*)(g_agg + (size_t)n * D))[q - 32];
    }

    const int eg = t >> 5;
    const int cg = t & 31;

    float acc[4][8];
    #pragma unroll
    for (int i = 0; i < 4; i++)
        #pragma unroll
        for (int j = 0; j < 8; j++) acc[i][j] = 0.f;

    for (int k0 = 0; k0 < 256; k0 += 32) {
        __syncthreads();
        #pragma unroll
        for (int i = t; i < 2048; i += 256)
            ((float4*)s_w)[i] = ((const float4*)W1)[k0 * 64 + i];
        __syncthreads();
        #pragma unroll
        for (int kk4 = 0; kk4 < 32; kk4 += 4) {
            float xs[4][4];
            #pragma unroll
            for (int i = 0; i < 4; i++) {
                float4 xv = *((const float4*)(s_in + (eg * 4 + i) * 256 + k0 + kk4));
                xs[i][0] = xv.x; xs[i][1] = xv.y; xs[i][2] = xv.z; xs[i][3] = xv.w;
            }
            #pragma unroll
            for (int u = 0; u < 4; u++) {
                const int kk = kk4 + u;
                float4 w0 = *((const float4*)(s_w + kk * 256 + cg * 4));
                float4 w1 = *((const float4*)(s_w + kk * 256 + 128 + cg * 4));
                #pragma unroll
                for (int i = 0; i < 4; i++) {
                    float xv = xs[i][u];
                    acc[i][0] = fmaf(xv, w0.x, acc[i][0]);
                    acc[i][1] = fmaf(xv, w0.y, acc[i][1]);
                    acc[i][2] = fmaf(xv, w0.z, acc[i][2]);
                    acc[i][3] = fmaf(xv, w0.w, acc[i][3]);
                    acc[i][4] = fmaf(xv, w1.x, acc[i][4]);
                    acc[i][5] = fmaf(xv, w1.y, acc[i][5]);
                    acc[i][6] = fmaf(xv, w1.z, acc[i][6]);
                    acc[i][7] = fmaf(xv, w1.w, acc[i][7]);
                }
            }
        }
    }

    float4 bb0 = *((const float4*)(b1 + cg * 4));
    float4 bb1 = *((const float4*)(b1 + 128 + cg * 4));

    __syncthreads();
    #pragma unroll
    for (int i = 0; i < 4; i++) {
        float4 r0, r1;
        r0.x = swishf(acc[i][0] + bb0.x);
        r0.y = swishf(acc[i][1] + bb0.y);
        r0.z = swishf(acc[i][2] + bb0.z);
        r0.w = swishf(acc[i][3] + bb0.w);
        r1.x = swishf(acc[i][4] + bb1.x);
        r1.y = swishf(acc[i][5] + bb1.y);
        r1.z = swishf(acc[i][6] + bb1.z);
        r1.w = swishf(acc[i][7] + bb1.w);
        *((float4*)(s_in + (eg * 4 + i) * 256 + cg * 4)) = r0;
        *((float4*)(s_in + (eg * 4 + i) * 256 + 128 + cg * 4)) = r1;
    }

    float a2[4][4];
    #pragma unroll
    for (int i = 0; i < 4; i++)
        #pragma unroll
        for (int j = 0; j < 4; j++) a2[i][j] = 0.f;

    for (int k0 = 0; k0 < 256; k0 += 32) {
        __syncthreads();
        #pragma unroll
        for (int i = t; i < 1024; i += 256)
            ((float4*)s_w)[i] = ((const float4*)W2)[k0 * 32 + i];
        __syncthreads();
        #pragma unroll
        for (int kk4 = 0; kk4 < 32; kk4 += 4) {
            float xs[4][4];
            #pragma unroll
            for (int i = 0; i < 4; i++) {
                float4 xv = *((const float4*)(s_in + (eg * 4 + i) * 256 + k0 + kk4));
                xs[i][0] = xv.x; xs[i][1] = xv.y; xs[i][2] = xv.z; xs[i][3] = xv.w;
            }
            #pragma unroll
            for (int u = 0; u < 4; u++) {
                const int kk = kk4 + u;
                float4 wv = *((const float4*)(s_w + kk * 128 + cg * 4));
                #pragma unroll
                for (int i = 0; i < 4; i++) {
                    float xv = xs[i][u];
                    a2[i][0] = fmaf(xv, wv.x, a2[i][0]);
                    a2[i][1] = fmaf(xv, wv.y, a2[i][1]);
                    a2[i][2] = fmaf(xv, wv.z, a2[i][2]);
                    a2[i][3] = fmaf(xv, wv.w, a2[i][3]);
                }
            }
        }
    }

    float4 bb = *((const float4*)(b2 + cg * 4));
    #pragma unroll
    for (int i = 0; i < 4; i++) {
        int n = n0 + eg * 4 + i;
        if (n < N_NODES) {
            float4* xp = (float4*)(g_x + (size_t)n * D + cg * 4);
            float4 o = *xp;
            o.x += a2[i][0] + bb.x;
            o.y += a2[i][1] + bb.y;
            o.z += a2[i][2] + bb.z;
            o.w += a2[i][3] + bb.w;
            *xp = o;
        }
    }
}

// ---------------- output head + graph pooling ---------------------------------
__global__ __launch_bounds__(256) void out_kernel(
    const float* __restrict__ W1, const float* __restrict__ b1,
    const float* __restrict__ w2, const float* __restrict__ b2,
    const int* __restrict__ batch, float* __restrict__ out)
{
    extern __shared__ float sm[];
    float* s_in = sm;        // [32][128]
    float* s_w  = sm + 4096; // [32][256]

    const int t  = threadIdx.x;
    const int n0 = blockIdx.x * 32;

    #pragma unroll
    for (int i = t; i < 1024; i += 256) {
        const int r = i >> 5, q = i & 31;
        int n = n0 + r; if (n >= N_NODES) n = N_NODES - 1;
        ((float4*)(s_in + r * 128))[q] = ((const float4*)(g_x + (size_t)n * D))[q];
    }

    const int eg = t >> 5;
    const int cg = t & 31;

    float acc[4][8];
    #pragma unroll
    for (int i = 0; i < 4; i++)
        #pragma unroll
        for (int j = 0; j < 8; j++) acc[i][j] = 0.f;

    for (int k0 = 0; k0 < 128; k0 += 32) {
        __syncthreads();
        #pragma unroll
        for (int i = t; i < 2048; i += 256)
            ((float4*)s_w)[i] = ((const float4*)W1)[k0 * 64 + i];
        __syncthreads();
        #pragma unroll
        for (int kk4 = 0; kk4 < 32; kk4 += 4) {
            float xs[4][4];
            #pragma unroll
            for (int i = 0; i < 4; i++) {
                float4 xv = *((const float4*)(s_in + (eg * 4 + i) * 128 + k0 + kk4));
                xs[i][0] = xv.x; xs[i][1] = xv.y; xs[i][2] = xv.z; xs[i][3] = xv.w;
            }
            #pragma unroll
            for (int u = 0; u < 4; u++) {
                const int kk = kk4 + u;
                float4 w0 = *((const float4*)(s_w + kk * 256 + cg * 4));
                float4 w1 = *((const float4*)(s_w + kk * 256 + 128 + cg * 4));
                #pragma unroll
                for (int i = 0; i < 4; i++) {
                    float xv = xs[i][u];
                    acc[i][0] = fmaf(xv, w0.x, acc[i][0]);
                    acc[i][1] = fmaf(xv, w0.y, acc[i][1]);
                    acc[i][2] = fmaf(xv, w0.z, acc[i][2]);
                    acc[i][3] = fmaf(xv, w0.w, acc[i][3]);
                    acc[i][4] = fmaf(xv, w1.x, acc[i][4]);
                    acc[i][5] = fmaf(xv, w1.y, acc[i][5]);
                    acc[i][6] = fmaf(xv, w1.z, acc[i][6]);
                    acc[i][7] = fmaf(xv, w1.w, acc[i][7]);
                }
            }
        }
    }

    float4 bb0 = *((const float4*)(b1 + cg * 4));
    float4 bb1 = *((const float4*)(b1 + 128 + cg * 4));
    float4 w2a = *((const float4*)(w2 + cg * 4));
    float4 w2b = *((const float4*)(w2 + 128 + cg * 4));

    float pv[4];
    #pragma unroll
    for (int i = 0; i < 4; i++) {
        float s = 0.f;
        s = fmaf(swishf(acc[i][0] + bb0.x), w2a.x, s);
        s = fmaf(swishf(acc[i][1] + bb0.y), w2a.y, s);
        s = fmaf(swishf(acc[i][2] + bb0.z), w2a.z, s);
        s = fmaf(swishf(acc[i][3] + bb0.w), w2a.w, s);
        s = fmaf(swishf(acc[i][4] + bb1.x), w2b.x, s);
        s = fmaf(swishf(acc[i][5] + bb1.y), w2b.y, s);
        s = fmaf(swishf(acc[i][6] + bb1.z), w2b.z, s);
        s = fmaf(swishf(acc[i][7] + bb1.w), w2b.w, s);
        pv[i] = s;
    }

    #pragma unroll
    for (int off = 16; off > 0; off >>= 1) {
        #pragma unroll
        for (int i = 0; i < 4; i++)
            pv[i] += __shfl_down_sync(0xffffffffu, pv[i], off);
    }

    if (cg == 0) {
        float bias = b2[0];
        #pragma unroll
        for (int i = 0; i < 4; i++) {
            int n = n0 + eg * 4 + i;
            if (n < N_NODES) atomicAdd(&out[batch[n]], pv[i] + bias);
        }
    }
}

// ---------------- host launcher ------------------------------------------------
extern "C" void kernel_launch(void* const* d_in, const int* in_sizes, int n_in,
                              void* d_out, int out_size) {
    const float *positions = 0, *edge_shift = 0, *lattice = 0, *embed = 0;
    const float *ew1 = 0, *eb1 = 0, *ew2 = 0, *eb2 = 0;
    const float *nw1 = 0, *nb1 = 0, *nw2 = 0, *nb2 = 0;
    const float *ow1 = 0, *ob1 = 0, *ow2 = 0, *ob2 = 0;
    const int *z = 0, *ei = 0, *batch = 0;

    // resolve inputs by element count (ambiguous sizes preserve order in both
    // plausible metadata orderings: edge_* before node_*, atomic before batch,
    // out_b1 before out_w2)
    for (int i = 0; i < n_in; i++) {
        int s = in_sizes[i];
        const void* p = d_in[i];
        switch (s) {
            case 150000:  positions  = (const float*)p; break;
            case 2400000: edge_shift = (const float*)p; break;
            case 288:     lattice    = (const float*)p; break;
            case 12800:   embed      = (const float*)p; break;
            case 197376:  ew1        = (const float*)p; break;
            case 196608:  nw1        = (const float*)p; break;
            case 32768:   ow1        = (const float*)p; break;
            case 768:     if (!eb1) eb1 = (const float*)p; else nb1 = (const float*)p; break;
            case 98304:   if (!ew2) ew2 = (const float*)p; else nw2 = (const float*)p; break;
            case 384:     if (!eb2) eb2 = (const float*)p; else nb2 = (const float*)p; break;
            case 256:     if (!ob1) ob1 = (const float*)p; else ow2 = (const float*)p; break;
            case 1:       ob2        = (const float*)p; break;
            case 1600000: ei         = (const int*)p; break;
            case 50000:   if (!z) z = (const int*)p; else batch = (const int*)p; break;
            default: break;
        }
    }

    const int EDGE_SMEM = 16384 * 4 + 32 * 4 + 64 * 4;  // 65920 B
    const int NODE_SMEM = 16384 * 4;                     // 65536 B
    const int OUT_SMEM  = (4096 + 8192) * 4;             // 49152 B
    cudaFuncSetAttribute(edge_kernel, cudaFuncAttributeMaxDynamicSharedMemorySize, EDGE_SMEM);
    cudaFuncSetAttribute(node_kernel, cudaFuncAttributeMaxDynamicSharedMemorySize, NODE_SMEM);
    cudaFuncSetAttribute(out_kernel,  cudaFuncAttributeMaxDynamicSharedMemorySize, OUT_SMEM);

    float* out = (float*)d_out;

    zero_out_kernel<<<1, 32>>>(out);
    d2_kernel<<<(N_EDGES + 255) / 256, 256>>>(positions, edge_shift, lattice, ei, batch);
    embed_kernel<<<(N_NODES * D + 255) / 256, 256>>>(embed, z);

    for (int l = 0; l < 3; l++) {
        zero_agg_kernel<<<(N_NODES * D + 255) / 256, 256>>>();
        edge_kernel<<<N_EDGES / 32, 256, EDGE_SMEM>>>(
            ew1 + (size_t)l * 257 * 256, eb1 + (size_t)l * 256,
            ew2 + (size_t)l * 256 * 128, eb2 + (size_t)l * 128, ei);
        node_kernel<<<(N_NODES + 31) / 32, 256, NODE_SMEM>>>(
            nw1 + (size_t)l * 256 * 256, nb1 + (size_t)l * 256,
            nw2 + (size_t)l * 256 * 128, nb2 + (size_t)l * 128);
    }

    out_kernel<<<(N_NODES + 31) / 32, 256, OUT_SMEM>>>(ow1, ob1, ow2, ob2, batch, out);
}

// round 4
// speedup vs baseline: 1.6474x; 1.6474x over previous
#include <cuda_runtime.h>
#include <cuda_bf16.h>
#include <stdint.h>

#define N_NODES 50000
#define N_EDGES 800000
#define N_GRAPHS 32
#define D 128
#define H 256

// Use tcgen05 only when compiling for an arch-accelerated target (sm_103a/sm_100a).
#if defined(__CUDA_ARCH__) && (defined(__CUDA_ARCH_FEAT_SM103_ALL) || defined(__CUDA_ARCH_FEAT_SM100_ALL) || defined(__CUDA_ARCH_FEAT_SM101_ALL))
#define USE_TC 1
#else
#define USE_TC 0
#endif

// ---------------- scratch (device globals) -----------------------------------
__device__ float g_x[N_NODES * D];
__device__ float g_agg[N_NODES * D];
__device__ float g_d2[N_EDGES];
// weights pre-converted to bf16 hi/lo, in blocked-atom SW128 SMEM-image order
__device__ __align__(128) __nv_bfloat16 g_w1h[3 * 256 * 256];
__device__ __align__(128) __nv_bfloat16 g_w1l[3 * 256 * 256];
__device__ __align__(128) __nv_bfloat16 g_w2h[3 * 256 * 128];
__device__ __align__(128) __nv_bfloat16 g_w2l[3 * 256 * 128];

__device__ __forceinline__ float swishf(float v) {
    return v / (1.f + __expf(-v));
}

__device__ __forceinline__ uint32_t packbf2(__nv_bfloat16 a, __nv_bfloat16 b) {
    __nv_bfloat162 t; t.x = a; t.y = b;
    return *reinterpret_cast<uint32_t*>(&t);
}

// ---------------- ptx helpers (tcgen05 path only) ------------------------------
__device__ __forceinline__ uint32_t smem_to_u32(const void* p) {
    uint32_t a;
    asm("{ .reg .u64 t; cvta.to.shared.u64 t, %1; cvt.u32.u64 %0, t; }" : "=r"(a) : "l"(p));
    return a;
}

#if USE_TC
__device__ __forceinline__ uint32_t elect_one_pred() {
    uint32_t pred;
    asm volatile(
        "{\n\t.reg .pred p;\n\telect.sync _|p, 0xFFFFFFFF;\n\tselp.b32 %0, 1, 0, p;\n\t}"
        : "=r"(pred));
    return pred;
}
#define TCGEN05_ALLOC(addr, n) \
    asm volatile("tcgen05.alloc.cta_group::1.sync.aligned.shared::cta.b32 [%0], %1;" \
                 :: "r"((uint32_t)(addr)), "r"((uint32_t)(n)) : "memory")
#define TCGEN05_DEALLOC(tm, n) \
    asm volatile("tcgen05.dealloc.cta_group::1.sync.aligned.b32 %0, %1;" :: "r"(tm), "r"((uint32_t)(n)))
#define TCGEN05_RELINQ() \
    asm volatile("tcgen05.relinquish_alloc_permit.cta_group::1.sync.aligned;")
#define TCGEN05_COMMIT(mb) \
    asm volatile("tcgen05.commit.cta_group::1.mbarrier::arrive::one.shared::cluster.b64 [%0];" \
                 :: "r"((uint32_t)(mb)) : "memory")
#define TCGEN05_WAIT_LD() asm volatile("tcgen05.wait::ld.sync.aligned;" ::: "memory")
#define TCGEN05_FENCE_AFTER() asm volatile("tcgen05.fence::after_thread_sync;" ::: "memory")
#define FENCE_ASYNC() asm volatile("fence.proxy.async.shared::cta;" ::: "memory")
#define MBARRIER_INIT(mb, cnt) \
    asm volatile("mbarrier.init.shared.b64 [%0], %1;" :: "r"((uint32_t)(mb)), "r"((uint32_t)(cnt)) : "memory")
#define MBARRIER_INVAL(mb) \
    asm volatile("mbarrier.inval.shared.b64 [%0];" :: "r"((uint32_t)(mb)) : "memory")
#define MBARRIER_WAIT_PARITY(mb, par) do { \
    uint32_t _mb = (uint32_t)(mb); uint32_t _p = (uint32_t)(par); uint32_t _done; \
    asm volatile("{\n\t.reg .pred p;\n\t" \
        "mbarrier.try_wait.parity.acquire.cta.shared::cta.b64 p, [%1], %2;\n\t" \
        "selp.b32 %0, 1, 0, p;\n\t}" : "=r"(_done) : "r"(_mb), "r"(_p) : "memory"); \
    if (!_done) { \
        asm volatile("{\n\t.reg .pred P1;\n\t" \
            "WL_%=:\n\t" \
            "mbarrier.try_wait.parity.acquire.cta.shared::cta.b64 P1, [%0], %1, 0x989680;\n\t" \
            "@P1 bra.uni WD_%=;\n\tbra.uni WL_%=;\n\tWD_%=:\n\t}" \
            :: "r"(_mb), "r"(_p) : "memory"); \
    } } while (0)
#define TCGEN05_LD_X32(r, addr) \
    asm volatile("tcgen05.ld.sync.aligned.32x32b.x32.b32 " \
        "{%0, %1, %2, %3, %4, %5, %6, %7, %8, %9, %10, %11, %12, %13, %14, %15, " \
        "%16, %17, %18, %19, %20, %21, %22, %23, %24, %25, %26, %27, %28, %29, %30, %31}, [%32];" \
        : "=r"((r)[0]), "=r"((r)[1]), "=r"((r)[2]), "=r"((r)[3]), \
          "=r"((r)[4]), "=r"((r)[5]), "=r"((r)[6]), "=r"((r)[7]), \
          "=r"((r)[8]), "=r"((r)[9]), "=r"((r)[10]), "=r"((r)[11]), \
          "=r"((r)[12]), "=r"((r)[13]), "=r"((r)[14]), "=r"((r)[15]), \
          "=r"((r)[16]), "=r"((r)[17]), "=r"((r)[18]), "=r"((r)[19]), \
          "=r"((r)[20]), "=r"((r)[21]), "=r"((r)[22]), "=r"((r)[23]), \
          "=r"((r)[24]), "=r"((r)[25]), "=r"((r)[26]), "=r"((r)[27]), \
          "=r"((r)[28]), "=r"((r)[29]), "=r"((r)[30]), "=r"((r)[31]) \
        : "r"(addr))

static constexpr uint64_t SMEM_DESC_BASE_SW128 =
    (uint64_t(2) << 61) | (uint64_t(1) << 46) | (uint64_t(64) << 32) | (uint64_t(1) << 16);
#define MAKE_SMEM_DESC(a) (SMEM_DESC_BASE_SW128 | ((uint64_t)((a) >> 4) & 0x3FFF))

__device__ __forceinline__ void mma_f16_ss(uint32_t d, uint64_t ad, uint64_t bd,
                                           uint32_t idesc, bool en) {
    uint32_t e = en ? 1u : 0u;
    asm volatile(
        "{\n\t.reg .pred p;\n\tsetp.ne.u32 p, %4, 0;\n\t"
        "tcgen05.mma.cta_group::1.kind::f16 [%0], %1, %2, %3, p;\n\t}"
        :: "r"(d), "l"(ad), "l"(bd), "r"(idesc), "r"(e) : "memory");
}

// idesc: F32 accum (1<<4), BF16 a/b (1<<7 | 1<<10), N>>3 <<17, M>>4 <<24
#define IDESC1 0x8400490u  /* M=128, N=256 */
#define IDESC2 0x8200490u  /* M=128, N=128 */
#endif  // USE_TC

// SMEM layout (bytes) for tcgen05 path
#define SM_A_HI 0
#define SM_A_LO 65536
#define SM_B_HI 131072
#define SM_B_LO 163840
#define SM_MISC 196608
#define EDGE_SMEM_BYTES (196608 + 4112)

// ---------------- small utility kernels ----------------------------------------
__global__ void zero_agg_kernel() {
    int i = blockIdx.x * blockDim.x + threadIdx.x;
    if (i < N_NODES * D) g_agg[i] = 0.f;
}
__global__ void zero_out_kernel(float* __restrict__ out) {
    if (threadIdx.x < N_GRAPHS) out[threadIdx.x] = 0.f;
}
__global__ void d2_kernel(const float* __restrict__ pos, const float* __restrict__ shift,
                          const float* __restrict__ lat, const int* __restrict__ ei,
                          const int* __restrict__ batch) {
    int e = blockIdx.x * blockDim.x + threadIdx.x;
    if (e >= N_EDGES) return;
    int s = ei[e];
    int d = ei[N_EDGES + e];
    int g = batch[s];
    const float* L = lat + g * 9;
    float sx = shift[e * 3 + 0], sy = shift[e * 3 + 1], sz = shift[e * 3 + 2];
    float vx = pos[d * 3 + 0] - pos[s * 3 + 0] + sx * L[0] + sy * L[3] + sz * L[6];
    float vy = pos[d * 3 + 1] - pos[s * 3 + 1] + sx * L[1] + sy * L[4] + sz * L[7];
    float vz = pos[d * 3 + 2] - pos[s * 3 + 2] + sx * L[2] + sy * L[5] + sz * L[8];
    g_d2[e] = vx * vx + vy * vy + vz * vz;
}
__global__ void embed_kernel(const float* __restrict__ embed, const int* __restrict__ z) {
    int i = blockIdx.x * blockDim.x + threadIdx.x;
    if (i >= N_NODES * D) return;
    int n = i >> 7, c = i & 127;
    g_x[i] = embed[z[n] * D + c];
}

// ---------------- weight conversion to bf16 hi/lo SMEM-image order -------------
__global__ void convert_w1(const float* __restrict__ ew1) {
    int i = blockIdx.x * blockDim.x + threadIdx.x;
    if (i >= 3 * 65536) return;
    int l = i >> 16, r = i & 65535, k = r >> 8, n = r & 255;
    float v = ew1[(size_t)l * 65792 + k * 256 + n];
    __nv_bfloat16 h = __float2bfloat16_rn(v);
    __nv_bfloat16 lo = __float2bfloat16_rn(v - __bfloat162float(h));
    uint32_t byte = ((uint32_t)(n >> 3) << 10) + ((n & 7) << 7) + ((k & 63) << 1);
    uint32_t sw = byte ^ ((byte >> 3) & 0x70);
    size_t idx = (size_t)l * 65536 + (size_t)(k >> 6) * 16384 + (sw >> 1);
    g_w1h[idx] = h; g_w1l[idx] = lo;
}
__global__ void convert_w2(const float* __restrict__ ew2) {
    int i = blockIdx.x * blockDim.x + threadIdx.x;
    if (i >= 3 * 32768) return;
    int l = i >> 15, r = i & 32767, k = r >> 7, n = r & 127;
    float v = ew2[(size_t)l * 32768 + k * 128 + n];
    __nv_bfloat16 h = __float2bfloat16_rn(v);
    __nv_bfloat16 lo = __float2bfloat16_rn(v - __bfloat162float(h));
    uint32_t byte = ((uint32_t)(n >> 3) << 10) + ((n & 7) << 7) + ((k & 63) << 1);
    uint32_t sw = byte ^ ((byte >> 3) & 0x70);
    size_t idx = (size_t)l * 32768 + (size_t)(k >> 6) * 8192 + (sw >> 1);
    g_w2h[idx] = h; g_w2l[idx] = lo;
}

// ---------------- fused edge MLP + scatter-add ---------------------------------
// 128 edges per CTA, 256 threads.
// USE_TC: bf16-split tcgen05 MMA (Ah*Bh + Ah*Bl + Al*Bh), fp32 TMEM accum.
// else:   proven fp32 FFMA path (4 sub-tiles of 32 edges).
__global__ __launch_bounds__(256) void edge_kernel(
    const float* __restrict__ W1f,   // fp32 W1 layer base [257,256]
    const float* __restrict__ b1,    // [256]
    const float* __restrict__ W2f,   // fp32 W2 layer base [256,128]
    const float* __restrict__ b2,    // [128]
    const int* __restrict__ ei, int layer)
{
#if USE_TC
    const float* w1r = W1f + 65536;  // W1 row 256 (d2 row)
    extern __shared__ __align__(1024) char smem[];
    char* smc = smem;
    const uint32_t sb = smem_to_u32(smem);
    const int t = threadIdx.x;
    const int wid = t >> 5;
    const int lane = t & 31;
    const int e0 = blockIdx.x * 128;

    int* s_dst   = (int*)(smc + SM_MISC + 16);
    int* s_src   = (int*)(smc + SM_MISC + 528);
    float* s_d2  = (float*)(smc + SM_MISC + 1040);
    float* s_b1  = (float*)(smc + SM_MISC + 1552);
    float* s_w1r = (float*)(smc + SM_MISC + 2576);
    float* s_b2  = (float*)(smc + SM_MISC + 3600);
    const uint32_t tmslot = sb + SM_MISC;
    const uint32_t mbar   = sb + SM_MISC + 8;

    if (wid == 7) TCGEN05_ALLOC(tmslot, 512);

    if (t < 128) {
        s_src[t] = ei[e0 + t];
        s_dst[t] = ei[N_EDGES + e0 + t];
        s_d2[t]  = g_d2[e0 + t];
        s_b2[t]  = b2[t];
    }
    s_b1[t]  = b1[t];
    s_w1r[t] = w1r[t];
    if (t == 0) MBARRIER_INIT(mbar, 1);
    __syncthreads();

    uint32_t tmem;
    asm volatile("ld.shared.b32 %0, [%1];" : "=r"(tmem) : "r"(tmslot));
    const uint32_t tmD1 = tmem;
    const uint32_t tmD2 = tmem + 256;

    // ---- gather ein (cols 0..127 = x[dst], 128..255 = x[src]) into A hi/lo ----
    for (int i = t; i < 128 * 64; i += 256) {
        const int m = i >> 6, q = i & 63;
        const float4* p = (q < 32)
            ? ((const float4*)(g_x + (size_t)s_dst[m] * D) + q)
            : ((const float4*)(g_x + (size_t)s_src[m] * D) + (q - 32));
        float4 v = *p;
        __nv_bfloat16 h0 = __float2bfloat16_rn(v.x), h1 = __float2bfloat16_rn(v.y);
        __nv_bfloat16 h2 = __float2bfloat16_rn(v.z), h3 = __float2bfloat16_rn(v.w);
        __nv_bfloat16 l0 = __float2bfloat16_rn(v.x - __bfloat162float(h0));
        __nv_bfloat16 l1 = __float2bfloat16_rn(v.y - __bfloat162float(h1));
        __nv_bfloat16 l2 = __float2bfloat16_rn(v.z - __bfloat162float(h2));
        __nv_bfloat16 l3 = __float2bfloat16_rn(v.w - __bfloat162float(h3));
        const int n0 = q * 4;
        uint32_t byte = ((uint32_t)((m >> 3) + ((n0 >> 6) << 4)) << 10)
                      + ((m & 7) << 7) + ((n0 & 63) << 1);
        uint32_t sw = byte ^ ((byte >> 3) & 0x70);
        uint2 hh; hh.x = packbf2(h0, h1); hh.y = packbf2(h2, h3);
        uint2 ll; ll.x = packbf2(l0, l1); ll.y = packbf2(l2, l3);
        *(uint2*)(smc + SM_A_HI + sw) = hh;
        *(uint2*)(smc + SM_A_LO + sw) = ll;
    }

    const uint64_t dAh = MAKE_SMEM_DESC(sb + SM_A_HI);
    const uint64_t dAl = MAKE_SMEM_DESC(sb + SM_A_LO);
    const uint64_t dBh = MAKE_SMEM_DESC(sb + SM_B_HI);
    const uint64_t dBl = MAKE_SMEM_DESC(sb + SM_B_LO);

    uint4* bH = (uint4*)(smc + SM_B_HI);
    uint4* bL = (uint4*)(smc + SM_B_LO);
    int ph = 0;

    // ---- GEMM1: D1[128,256] = ein @ W1 (K=256, 4 chunks of 64) ----
    for (int c = 0; c < 4; c++) {
        const uint4* wh = (const uint4*)g_w1h + ((size_t)layer * 65536 + (size_t)c * 16384) / 8;
        const uint4* wl = (const uint4*)g_w1l + ((size_t)layer * 65536 + (size_t)c * 16384) / 8;
        for (int i = t; i < 2048; i += 256) { bH[i] = wh[i]; bL[i] = wl[i]; }
        FENCE_ASYNC();
        __syncthreads();
        if (wid == 7) {
            if (elect_one_pred()) {
                #pragma unroll
                for (int kk = 0; kk < 4; kk++) {
                    const int s = c * 4 + kk;
                    const uint32_t aoff = (uint32_t)(s >> 2) * 1024 + (s & 3) * 2;
                    const uint32_t boff = kk * 2;
                    mma_f16_ss(tmD1, dAh + aoff, dBh + boff, IDESC1, !(c == 0 && kk == 0));
                    mma_f16_ss(tmD1, dAh + aoff, dBl + boff, IDESC1, true);
                    mma_f16_ss(tmD1, dAl + aoff, dBh + boff, IDESC1, true);
                }
                TCGEN05_COMMIT(mbar);
            }
        }
        MBARRIER_WAIT_PARITY(mbar, ph & 1); ph++;
    }
    TCGEN05_FENCE_AFTER();

    // ---- epilogue 1: m1 = swish(D1 + b1 + d2*w1r) -> A hi/lo (warps 0-3);
    //      warps 4-7 prefetch W2 chunk 0 ----
    if (wid < 4) {
        const int row = wid * 32 + lane;
        const float d2m = s_d2[row];
        #pragma unroll
        for (int cb = 0; cb < 8; cb++) {
            uint32_t r[32];
            TCGEN05_LD_X32(r, tmD1 + cb * 32);
            TCGEN05_WAIT_LD();
            #pragma unroll
            for (int j = 0; j < 32; j += 2) {
                const int n = cb * 32 + j;
                float v0 = swishf(__uint_as_float(r[j])     + s_b1[n]     + d2m * s_w1r[n]);
                float v1 = swishf(__uint_as_float(r[j + 1]) + s_b1[n + 1] + d2m * s_w1r[n + 1]);
                __nv_bfloat16 h0 = __float2bfloat16_rn(v0), h1 = __float2bfloat16_rn(v1);
                __nv_bfloat16 l0 = __float2bfloat16_rn(v0 - __bfloat162float(h0));
                __nv_bfloat16 l1 = __float2bfloat16_rn(v1 - __bfloat162float(h1));
                uint32_t byte = ((uint32_t)((row >> 3) + ((n >> 6) << 4)) << 10)
                              + ((row & 7) << 7) + ((n & 63) << 1);
                uint32_t sw = byte ^ ((byte >> 3) & 0x70);
                *(uint32_t*)(smc + SM_A_HI + sw) = packbf2(h0, h1);
                *(uint32_t*)(smc + SM_A_LO + sw) = packbf2(l0, l1);
            }
        }
    } else {
        const uint4* wh = (const uint4*)g_w2h + ((size_t)layer * 32768) / 8;
        const uint4* wl = (const uint4*)g_w2l + ((size_t)layer * 32768) / 8;
        for (int i = t - 128; i < 1024; i += 128) { bH[i] = wh[i]; bL[i] = wl[i]; }
    }
    FENCE_ASYNC();
    __syncthreads();

    // ---- GEMM2: D2[128,128] = m1 @ W2 (K=256, 4 chunks) ----
    for (int c = 0; c < 4; c++) {
        if (c > 0) {
            const uint4* wh = (const uint4*)g_w2h + ((size_t)layer * 32768 + (size_t)c * 8192) / 8;
            const uint4* wl = (const uint4*)g_w2l + ((size_t)layer * 32768 + (size_t)c * 8192) / 8;
            for (int i = t; i < 1024; i += 256) { bH[i] = wh[i]; bL[i] = wl[i]; }
            FENCE_ASYNC();
        }
        __syncthreads();
        if (wid == 7) {
            if (elect_one_pred()) {
                #pragma unroll
                for (int kk = 0; kk < 4; kk++) {
                    const int s = c * 4 + kk;
                    const uint32_t aoff = (uint32_t)(s >> 2) * 1024 + (s & 3) * 2;
                    const uint32_t boff = kk * 2;
                    mma_f16_ss(tmD2, dAh + aoff, dBh + boff, IDESC2, !(c == 0 && kk == 0));
                    mma_f16_ss(tmD2, dAh + aoff, dBl + boff, IDESC2, true);
                    mma_f16_ss(tmD2, dAl + aoff, dBh + boff, IDESC2, true);
                }
                TCGEN05_COMMIT(mbar);
            }
        }
        MBARRIER_WAIT_PARITY(mbar, ph & 1); ph++;
    }
    TCGEN05_FENCE_AFTER();

    // ---- epilogue 2: m2 = swish(D2 + b2) -> atomic scatter to agg[dst] ----
    if (wid < 4) {
        const int row = wid * 32 + lane;
        float* arow = g_agg + (size_t)s_dst[row] * D;
        #pragma unroll
        for (int cb = 0; cb < 4; cb++) {
            uint32_t r[32];
            TCGEN05_LD_X32(r, tmD2 + cb * 32);
            TCGEN05_WAIT_LD();
            #pragma unroll
            for (int j = 0; j < 32; j += 4) {
                const int n = cb * 32 + j;
                float v0 = swishf(__uint_as_float(r[j])     + s_b2[n]);
                float v1 = swishf(__uint_as_float(r[j + 1]) + s_b2[n + 1]);
                float v2 = swishf(__uint_as_float(r[j + 2]) + s_b2[n + 2]);
                float v3 = swishf(__uint_as_float(r[j + 3]) + s_b2[n + 3]);
                asm volatile("red.global.add.v4.f32 [%0], {%1, %2, %3, %4};"
                             :: "l"(arow + n), "f"(v0), "f"(v1), "f"(v2), "f"(v3)
                             : "memory");
            }
        }
    }

    __syncthreads();
    if (t == 0) MBARRIER_INVAL(mbar);
    __syncthreads();
    if (wid == 7) {
        TCGEN05_RELINQ();
        TCGEN05_DEALLOC(tmem, 512);
    }

#else  // ---------------- fp32 FFMA fallback (proven R2 path, 4x 32-edge subs) ----
    extern __shared__ float sm[];
    float* s_in = sm;                       // [32][256]
    float* s_w  = sm + 8192;                // weight staging
    float* s_d2 = sm + 16384;               // [32]
    int*   s_src = (int*)(sm + 16384 + 32); // [32]
    int*   s_dst = s_src + 32;              // [32]

    const int t  = threadIdx.x;
    const int eg = t >> 5;
    const int cg = t & 31;
    (void)layer;

    for (int sub = 0; sub < 4; sub++) {
        const int e0 = blockIdx.x * 128 + sub * 32;
        __syncthreads();
        if (t < 32) {
            s_src[t] = ei[e0 + t];
            s_dst[t] = ei[N_EDGES + e0 + t];
            s_d2[t]  = g_d2[e0 + t];
        }
        __syncthreads();

        for (int i = t; i < 32 * 64; i += 256) {
            const int e = i >> 6, q = i & 63;
            const float4* p = (q < 32)
                ? ((const float4*)(g_x + (size_t)s_dst[e] * D) + q)
                : ((const float4*)(g_x + (size_t)s_src[e] * D) + (q - 32));
            ((float4*)(s_in + e * 256))[q] = *p;
        }

        float acc[4][8];
        #pragma unroll
        for (int i = 0; i < 4; i++)
            #pragma unroll
            for (int j = 0; j < 8; j++) acc[i][j] = 0.f;

        for (int k0 = 0; k0 < 256; k0 += 32) {
            __syncthreads();
            #pragma unroll
            for (int i = t; i < 2048; i += 256)
                ((float4*)s_w)[i] = ((const float4*)W1f)[k0 * 64 + i];
            __syncthreads();
            #pragma unroll
            for (int kk4 = 0; kk4 < 32; kk4 += 4) {
                float xs[4][4];
                #pragma unroll
                for (int i = 0; i < 4; i++) {
                    float4 xv = *((const float4*)(s_in + (eg * 4 + i) * 256 + k0 + kk4));
                    xs[i][0] = xv.x; xs[i][1] = xv.y; xs[i][2] = xv.z; xs[i][3] = xv.w;
                }
                #pragma unroll
                for (int u = 0; u < 4; u++) {
                    const int kk = kk4 + u;
                    float4 w0 = *((const float4*)(s_w + kk * 256 + cg * 4));
                    float4 w1 = *((const float4*)(s_w + kk * 256 + 128 + cg * 4));
                    #pragma unroll
                    for (int i = 0; i < 4; i++) {
                        float xv = xs[i][u];
                        acc[i][0] = fmaf(xv, w0.x, acc[i][0]);
                        acc[i][1] = fmaf(xv, w0.y, acc[i][1]);
                        acc[i][2] = fmaf(xv, w0.z, acc[i][2]);
                        acc[i][3] = fmaf(xv, w0.w, acc[i][3]);
                        acc[i][4] = fmaf(xv, w1.x, acc[i][4]);
                        acc[i][5] = fmaf(xv, w1.y, acc[i][5]);
                        acc[i][6] = fmaf(xv, w1.z, acc[i][6]);
                        acc[i][7] = fmaf(xv, w1.w, acc[i][7]);
                    }
                }
            }
        }

        float4 wd0 = *((const float4*)(W1f + 256 * 256 + cg * 4));
        float4 wd1 = *((const float4*)(W1f + 256 * 256 + 128 + cg * 4));
        float4 bb0 = *((const float4*)(b1 + cg * 4));
        float4 bb1 = *((const float4*)(b1 + 128 + cg * 4));

        __syncthreads();
        #pragma unroll
        for (int i = 0; i < 4; i++) {
            float dv = s_d2[eg * 4 + i];
            float4 r0, r1;
            r0.x = swishf(fmaf(dv, wd0.x, acc[i][0]) + bb0.x);
            r0.y = swishf(fmaf(dv, wd0.y, acc[i][1]) + bb0.y);
            r0.z = swishf(fmaf(dv, wd0.z, acc[i][2]) + bb0.z);
            r0.w = swishf(fmaf(dv, wd0.w, acc[i][3]) + bb0.w);
            r1.x = swishf(fmaf(dv, wd1.x, acc[i][4]) + bb1.x);
            r1.y = swishf(fmaf(dv, wd1.y, acc[i][5]) + bb1.y);
            r1.z = swishf(fmaf(dv, wd1.z, acc[i][6]) + bb1.z);
            r1.w = swishf(fmaf(dv, wd1.w, acc[i][7]) + bb1.w);
            *((float4*)(s_in + (eg * 4 + i) * 256 + cg * 4)) = r0;
            *((float4*)(s_in + (eg * 4 + i) * 256 + 128 + cg * 4)) = r1;
        }

        float a2[4][4];
        #pragma unroll
        for (int i = 0; i < 4; i++)
            #pragma unroll
            for (int j = 0; j < 4; j++) a2[i][j] = 0.f;

        for (int k0 = 0; k0 < 256; k0 += 32) {
            __syncthreads();
            #pragma unroll
            for (int i = t; i < 1024; i += 256)
                ((float4*)s_w)[i] = ((const float4*)W2f)[k0 * 32 + i];
            __syncthreads();
            #pragma unroll
            for (int kk4 = 0; kk4 < 32; kk4 += 4) {
                float xs[4][4];
                #pragma unroll
                for (int i = 0; i < 4; i++) {
                    float4 xv = *((const float4*)(s_in + (eg * 4 + i) * 256 + k0 + kk4));
                    xs[i][0] = xv.x; xs[i][1] = xv.y; xs[i][2] = xv.z; xs[i][3] = xv.w;
                }
                #pragma unroll
                for (int u = 0; u < 4; u++) {
                    const int kk = kk4 + u;
                    float4 wv = *((const float4*)(s_w + kk * 128 + cg * 4));
                    #pragma unroll
                    for (int i = 0; i < 4; i++) {
                        float xv = xs[i][u];
                        a2[i][0] = fmaf(xv, wv.x, a2[i][0]);
                        a2[i][1] = fmaf(xv, wv.y, a2[i][1]);
                        a2[i][2] = fmaf(xv, wv.z, a2[i][2]);
                        a2[i][3] = fmaf(xv, wv.w, a2[i][3]);
                    }
                }
            }
        }

        float4 bb = *((const float4*)(b2 + cg * 4));
        #pragma unroll
        for (int i = 0; i < 4; i++) {
            float* ap = g_agg + (size_t)s_dst[eg * 4 + i] * D + cg * 4;
            atomicAdd(ap + 0, swishf(a2[i][0] + bb.x));
            atomicAdd(ap + 1, swishf(a2[i][1] + bb.y));
            atomicAdd(ap + 2, swishf(a2[i][2] + bb.z));
            atomicAdd(ap + 3, swishf(a2[i][3] + bb.w));
        }
    }
#endif
}

// ---------------- fp32 node MLP (residual) -------------------------------------
__global__ __launch_bounds__(256) void node_kernel(
    const float* __restrict__ W1, const float* __restrict__ b1,
    const float* __restrict__ W2, const float* __restrict__ b2)
{
    extern __shared__ float sm[];
    float* s_in = sm;
    float* s_w  = sm + 8192;

    const int t  = threadIdx.x;
    const int n0 = blockIdx.x * 32;

    #pragma unroll
    for (int i = t; i < 32 * 64; i += 256) {
        const int r = i >> 6, q = i & 63;
        int n = n0 + r; if (n >= N_NODES) n = N_NODES - 1;
        ((float4*)(s_in + r * 256))[q] = (q < 32)
            ? ((const float4*)(g_x + (size_t)n * D))[q]
            : ((const float4*)(g_agg + (size_t)n * D))[q - 32];
    }

    const int eg = t >> 5;
    const int cg = t & 31;

    float acc[4][8];
    #pragma unroll
    for (int i = 0; i < 4; i++)
        #pragma unroll
        for (int j = 0; j < 8; j++) acc[i][j] = 0.f;

    for (int k0 = 0; k0 < 256; k0 += 32) {
        __syncthreads();
        #pragma unroll
        for (int i = t; i < 2048; i += 256)
            ((float4*)s_w)[i] = ((const float4*)W1)[k0 * 64 + i];
        __syncthreads();
        #pragma unroll
        for (int kk4 = 0; kk4 < 32; kk4 += 4) {
            float xs[4][4];
            #pragma unroll
            for (int i = 0; i < 4; i++) {
                float4 xv = *((const float4*)(s_in + (eg * 4 + i) * 256 + k0 + kk4));
                xs[i][0] = xv.x; xs[i][1] = xv.y; xs[i][2] = xv.z; xs[i][3] = xv.w;
            }
            #pragma unroll
            for (int u = 0; u < 4; u++) {
                const int kk = kk4 + u;
                float4 w0 = *((const float4*)(s_w + kk * 256 + cg * 4));
                float4 w1 = *((const float4*)(s_w + kk * 256 + 128 + cg * 4));
                #pragma unroll
                for (int i = 0; i < 4; i++) {
                    float xv = xs[i][u];
                    acc[i][0] = fmaf(xv, w0.x, acc[i][0]);
                    acc[i][1] = fmaf(xv, w0.y, acc[i][1]);
                    acc[i][2] = fmaf(xv, w0.z, acc[i][2]);
                    acc[i][3] = fmaf(xv, w0.w, acc[i][3]);
                    acc[i][4] = fmaf(xv, w1.x, acc[i][4]);
                    acc[i][5] = fmaf(xv, w1.y, acc[i][5]);
                    acc[i][6] = fmaf(xv, w1.z, acc[i][6]);
                    acc[i][7] = fmaf(xv, w1.w, acc[i][7]);
                }
            }
        }
    }

    float4 bb0 = *((const float4*)(b1 + cg * 4));
    float4 bb1 = *((const float4*)(b1 + 128 + cg * 4));

    __syncthreads();
    #pragma unroll
    for (int i = 0; i < 4; i++) {
        float4 r0, r1;
        r0.x = swishf(acc[i][0] + bb0.x);
        r0.y = swishf(acc[i][1] + bb0.y);
        r0.z = swishf(acc[i][2] + bb0.z);
        r0.w = swishf(acc[i][3] + bb0.w);
        r1.x = swishf(acc[i][4] + bb1.x);
        r1.y = swishf(acc[i][5] + bb1.y);
        r1.z = swishf(acc[i][6] + bb1.z);
        r1.w = swishf(acc[i][7] + bb1.w);
        *((float4*)(s_in + (eg * 4 + i) * 256 + cg * 4)) = r0;
        *((float4*)(s_in + (eg * 4 + i) * 256 + 128 + cg * 4)) = r1;
    }

    float a2[4][4];
    #pragma unroll
    for (int i = 0; i < 4; i++)
        #pragma unroll
        for (int j = 0; j < 4; j++) a2[i][j] = 0.f;

    for (int k0 = 0; k0 < 256; k0 += 32) {
        __syncthreads();
        #pragma unroll
        for (int i = t; i < 1024; i += 256)
            ((float4*)s_w)[i] = ((const float4*)W2)[k0 * 32 + i];
        __syncthreads();
        #pragma unroll
        for (int kk4 = 0; kk4 < 32; kk4 += 4) {
            float xs[4][4];
            #pragma unroll
            for (int i = 0; i < 4; i++) {
                float4 xv = *((const float4*)(s_in + (eg * 4 + i) * 256 + k0 + kk4));
                xs[i][0] = xv.x; xs[i][1] = xv.y; xs[i][2] = xv.z; xs[i][3] = xv.w;
            }
            #pragma unroll
            for (int u = 0; u < 4; u++) {
                const int kk = kk4 + u;
                float4 wv = *((const float4*)(s_w + kk * 128 + cg * 4));
                #pragma unroll
                for (int i = 0; i < 4; i++) {
                    float xv = xs[i][u];
                    a2[i][0] = fmaf(xv, wv.x, a2[i][0]);
                    a2[i][1] = fmaf(xv, wv.y, a2[i][1]);
                    a2[i][2] = fmaf(xv, wv.z, a2[i][2]);
                    a2[i][3] = fmaf(xv, wv.w, a2[i][3]);
                }
            }
        }
    }

    float4 bb = *((const float4*)(b2 + cg * 4));
    #pragma unroll
    for (int i = 0; i < 4; i++) {
        int n = n0 + eg * 4 + i;
        if (n < N_NODES) {
            float4* xp = (float4*)(g_x + (size_t)n * D + cg * 4);
            float4 o = *xp;
            o.x += a2[i][0] + bb.x;
            o.y += a2[i][1] + bb.y;
            o.z += a2[i][2] + bb.z;
            o.w += a2[i][3] + bb.w;
            *xp = o;
        }
    }
}

// ---------------- output head + graph pooling ----------------------------------
__global__ __launch_bounds__(256) void out_kernel(
    const float* __restrict__ W1, const float* __restrict__ b1,
    const float* __restrict__ w2, const float* __restrict__ b2,
    const int* __restrict__ batch, float* __restrict__ out)
{
    extern __shared__ float sm[];
    float* s_in = sm;
    float* s_w  = sm + 4096;

    const int t  = threadIdx.x;
    const int n0 = blockIdx.x * 32;

    #pragma unroll
    for (int i = t; i < 1024; i += 256) {
        const int r = i >> 5, q = i & 31;
        int n = n0 + r; if (n >= N_NODES) n = N_NODES - 1;
        ((float4*)(s_in + r * 128))[q] = ((const float4*)(g_x + (size_t)n * D))[q];
    }

    const int eg = t >> 5;
    const int cg = t & 31;

    float acc[4][8];
    #pragma unroll
    for (int i = 0; i < 4; i++)
        #pragma unroll
        for (int j = 0; j < 8; j++) acc[i][j] = 0.f;

    for (int k0 = 0; k0 < 128; k0 += 32) {
        __syncthreads();
        #pragma unroll
        for (int i = t; i < 2048; i += 256)
            ((float4*)s_w)[i] = ((const float4*)W1)[k0 * 64 + i];
        __syncthreads();
        #pragma unroll
        for (int kk4 = 0; kk4 < 32; kk4 += 4) {
            float xs[4][4];
            #pragma unroll
            for (int i = 0; i < 4; i++) {
                float4 xv = *((const float4*)(s_in + (eg * 4 + i) * 128 + k0 + kk4));
                xs[i][0] = xv.x; xs[i][1] = xv.y; xs[i][2] = xv.z; xs[i][3] = xv.w;
            }
            #pragma unroll
            for (int u = 0; u < 4; u++) {
                const int kk = kk4 + u;
                float4 w0 = *((const float4*)(s_w + kk * 256 + cg * 4));
                float4 w1 = *((const float4*)(s_w + kk * 256 + 128 + cg * 4));
                #pragma unroll
                for (int i = 0; i < 4; i++) {
                    float xv = xs[i][u];
                    acc[i][0] = fmaf(xv, w0.x, acc[i][0]);
                    acc[i][1] = fmaf(xv, w0.y, acc[i][1]);
                    acc[i][2] = fmaf(xv, w0.z, acc[i][2]);
                    acc[i][3] = fmaf(xv, w0.w, acc[i][3]);
                    acc[i][4] = fmaf(xv, w1.x, acc[i][4]);
                    acc[i][5] = fmaf(xv, w1.y, acc[i][5]);
                    acc[i][6] = fmaf(xv, w1.z, acc[i][6]);
                    acc[i][7] = fmaf(xv, w1.w, acc[i][7]);
                }
            }
        }
    }

    float4 bb0 = *((const float4*)(b1 + cg * 4));
    float4 bb1 = *((const float4*)(b1 + 128 + cg * 4));
    float4 w2a = *((const float4*)(w2 + cg * 4));
    float4 w2b = *((const float4*)(w2 + 128 + cg * 4));

    float pv[4];
    #pragma unroll
    for (int i = 0; i < 4; i++) {
        float s = 0.f;
        s = fmaf(swishf(acc[i][0] + bb0.x), w2a.x, s);
        s = fmaf(swishf(acc[i][1] + bb0.y), w2a.y, s);
        s = fmaf(swishf(acc[i][2] + bb0.z), w2a.z, s);
        s = fmaf(swishf(acc[i][3] + bb0.w), w2a.w, s);
        s = fmaf(swishf(acc[i][4] + bb1.x), w2b.x, s);
        s = fmaf(swishf(acc[i][5] + bb1.y), w2b.y, s);
        s = fmaf(swishf(acc[i][6] + bb1.z), w2b.z, s);
        s = fmaf(swishf(acc[i][7] + bb1.w), w2b.w, s);
        pv[i] = s;
    }

    #pragma unroll
    for (int off = 16; off > 0; off >>= 1) {
        #pragma unroll
        for (int i = 0; i < 4; i++)
            pv[i] += __shfl_down_sync(0xffffffffu, pv[i], off);
    }

    if (cg == 0) {
        float bias = b2[0];
        #pragma unroll
        for (int i = 0; i < 4; i++) {
            int n = n0 + eg * 4 + i;
            if (n < N_NODES) atomicAdd(&out[batch[n]], pv[i] + bias);
        }
    }
}

// ---------------- host launcher ------------------------------------------------
extern "C" void kernel_launch(void* const* d_in, const int* in_sizes, int n_in,
                              void* d_out, int out_size) {
    const float *positions = 0, *edge_shift = 0, *lattice = 0, *embed = 0;
    const float *ew1 = 0, *eb1 = 0, *ew2 = 0, *eb2 = 0;
    const float *nw1 = 0, *nb1 = 0, *nw2 = 0, *nb2 = 0;
    const float *ow1 = 0, *ob1 = 0, *ow2 = 0, *ob2 = 0;
    const int *z = 0, *ei = 0, *batch = 0;

    for (int i = 0; i < n_in; i++) {
        int s = in_sizes[i];
        const void* p = d_in[i];
        switch (s) {
            case 150000:  positions  = (const float*)p; break;
            case 2400000: edge_shift = (const float*)p; break;
            case 288:     lattice    = (const float*)p; break;
            case 12800:   embed      = (const float*)p; break;
            case 197376:  ew1        = (const float*)p; break;
            case 196608:  nw1        = (const float*)p; break;
            case 32768:   ow1        = (const float*)p; break;
            case 768:     if (!eb1) eb1 = (const float*)p; else nb1 = (const float*)p; break;
            case 98304:   if (!ew2) ew2 = (const float*)p; else nw2 = (const float*)p; break;
            case 384:     if (!eb2) eb2 = (const float*)p; else nb2 = (const float*)p; break;
            case 256:     if (!ob1) ob1 = (const float*)p; else ow2 = (const float*)p; break;
            case 1:       ob2        = (const float*)p; break;
            case 1600000: ei         = (const int*)p; break;
            case 50000:   if (!z) z = (const int*)p; else batch = (const int*)p; break;
            default: break;
        }
    }

    const int NODE_SMEM = 16384 * 4;
    const int OUT_SMEM  = (4096 + 8192) * 4;
    cudaFuncSetAttribute(edge_kernel, cudaFuncAttributeMaxDynamicSharedMemorySize, EDGE_SMEM_BYTES);
    cudaFuncSetAttribute(node_kernel, cudaFuncAttributeMaxDynamicSharedMemorySize, NODE_SMEM);
    cudaFuncSetAttribute(out_kernel,  cudaFuncAttributeMaxDynamicSharedMemorySize, OUT_SMEM);

    float* out = (float*)d_out;

    zero_out_kernel<<<1, 32>>>(out);
    d2_kernel<<<(N_EDGES + 255) / 256, 256>>>(positions, edge_shift, lattice, ei, batch);
    embed_kernel<<<(N_NODES * D + 255) / 256, 256>>>(embed, z);
    convert_w1<<<(3 * 65536 + 255) / 256, 256>>>(ew1);
    convert_w2<<<(3 * 32768 + 255) / 256, 256>>>(ew2);

    for (int l = 0; l < 3; l++) {
        zero_agg_kernel<<<(N_NODES * D + 255) / 256, 256>>>();
        edge_kernel<<<N_EDGES / 128, 256, EDGE_SMEM_BYTES>>>(
            ew1 + (size_t)l * 65792, eb1 + (size_t)l * 256,
            ew2 + (size_t)l * 32768, eb2 + (size_t)l * 128, ei, l);
        node_kernel<<<(N_NODES + 31) / 32, 256, NODE_SMEM>>>(
            nw1 + (size_t)l * 256 * 256, nb1 + (size_t)l * 256,
            nw2 + (size_t)l * 256 * 128, nb2 + (size_t)l * 128);
    }

    out_kernel<<<(N_NODES + 31) / 32, 256, OUT_SMEM>>>(ow1, ob1, ow2, ob2, batch, out);
}

// round 5
// speedup vs baseline: 1.6507x; 1.0020x over previous
#include <cuda_runtime.h>
#include <cuda_bf16.h>
#include <stdint.h>

#define N_NODES 50000
#define N_EDGES 800000
#define N_GRAPHS 32
#define D 128
#define H 256

// Use tcgen05 only when compiling for an arch-accelerated target (sm_103a/sm_100a).
#if defined(__CUDA_ARCH__) && (defined(__CUDA_ARCH_FEAT_SM103_ALL) || defined(__CUDA_ARCH_FEAT_SM100_ALL) || defined(__CUDA_ARCH_FEAT_SM101_ALL))
#define USE_TC 1
#else
#define USE_TC 0
#endif

// ---------------- scratch (device globals) -----------------------------------
__device__ float g_x[N_NODES * D];
__device__ float g_agg[N_NODES * D];
__device__ float g_d2[N_EDGES];
// weights pre-converted to bf16 hi/lo, in blocked-atom SW128 SMEM-image order
__device__ __align__(128) __nv_bfloat16 g_w1h[3 * 256 * 256];
__device__ __align__(128) __nv_bfloat16 g_w1l[3 * 256 * 256];
__device__ __align__(128) __nv_bfloat16 g_w2h[3 * 256 * 128];
__device__ __align__(128) __nv_bfloat16 g_w2l[3 * 256 * 128];

__device__ __forceinline__ float swishf(float v) {
    return v / (1.f + __expf(-v));
}

__device__ __forceinline__ uint32_t packbf2(__nv_bfloat16 a, __nv_bfloat16 b) {
    __nv_bfloat162 t; t.x = a; t.y = b;
    return *reinterpret_cast<uint32_t*>(&t);
}

// ---------------- ptx helpers (tcgen05 path only) ------------------------------
__device__ __forceinline__ uint32_t smem_to_u32(const void* p) {
    uint32_t a;
    asm("{ .reg .u64 t; cvta.to.shared.u64 t, %1; cvt.u32.u64 %0, t; }" : "=r"(a) : "l"(p));
    return a;
}

#if USE_TC
__device__ __forceinline__ uint32_t elect_one_pred() {
    uint32_t pred;
    asm volatile(
        "{\n\t.reg .pred p;\n\telect.sync _|p, 0xFFFFFFFF;\n\tselp.b32 %0, 1, 0, p;\n\t}"
        : "=r"(pred));
    return pred;
}
#define TCGEN05_ALLOC(addr, n) \
    asm volatile("tcgen05.alloc.cta_group::1.sync.aligned.shared::cta.b32 [%0], %1;" \
                 :: "r"((uint32_t)(addr)), "r"((uint32_t)(n)) : "memory")
#define TCGEN05_DEALLOC(tm, n) \
    asm volatile("tcgen05.dealloc.cta_group::1.sync.aligned.b32 %0, %1;" :: "r"(tm), "r"((uint32_t)(n)))
#define TCGEN05_RELINQ() \
    asm volatile("tcgen05.relinquish_alloc_permit.cta_group::1.sync.aligned;")
#define TCGEN05_COMMIT(mb) \
    asm volatile("tcgen05.commit.cta_group::1.mbarrier::arrive::one.shared::cluster.b64 [%0];" \
                 :: "r"((uint32_t)(mb)) : "memory")
#define TCGEN05_WAIT_LD() asm volatile("tcgen05.wait::ld.sync.aligned;" ::: "memory")
#define TCGEN05_FENCE_AFTER() asm volatile("tcgen05.fence::after_thread_sync;" ::: "memory")
#define FENCE_ASYNC() asm volatile("fence.proxy.async.shared::cta;" ::: "memory")
#define MBARRIER_INIT(mb, cnt) \
    asm volatile("mbarrier.init.shared.b64 [%0], %1;" :: "r"((uint32_t)(mb)), "r"((uint32_t)(cnt)) : "memory")
#define MBARRIER_INVAL(mb) \
    asm volatile("mbarrier.inval.shared.b64 [%0];" :: "r"((uint32_t)(mb)) : "memory")
#define MBARRIER_WAIT_PARITY(mb, par) do { \
    uint32_t _mb = (uint32_t)(mb); uint32_t _p = (uint32_t)(par); uint32_t _done; \
    asm volatile("{\n\t.reg .pred p;\n\t" \
        "mbarrier.try_wait.parity.acquire.cta.shared::cta.b64 p, [%1], %2;\n\t" \
        "selp.b32 %0, 1, 0, p;\n\t}" : "=r"(_done) : "r"(_mb), "r"(_p) : "memory"); \
    if (!_done) { \
        asm volatile("{\n\t.reg .pred P1;\n\t" \
            "WL_%=:\n\t" \
            "mbarrier.try_wait.parity.acquire.cta.shared::cta.b64 P1, [%0], %1, 0x989680;\n\t" \
            "@P1 bra.uni WD_%=;\n\tbra.uni WL_%=;\n\tWD_%=:\n\t}" \
            :: "r"(_mb), "r"(_p) : "memory"); \
    } } while (0)
#define TCGEN05_LD_X32(r, addr) \
    asm volatile("tcgen05.ld.sync.aligned.32x32b.x32.b32 " \
        "{%0, %1, %2, %3, %4, %5, %6, %7, %8, %9, %10, %11, %12, %13, %14, %15, " \
        "%16, %17, %18, %19, %20, %21, %22, %23, %24, %25, %26, %27, %28, %29, %30, %31}, [%32];" \
        : "=r"((r)[0]), "=r"((r)[1]), "=r"((r)[2]), "=r"((r)[3]), \
          "=r"((r)[4]), "=r"((r)[5]), "=r"((r)[6]), "=r"((r)[7]), \
          "=r"((r)[8]), "=r"((r)[9]), "=r"((r)[10]), "=r"((r)[11]), \
          "=r"((r)[12]), "=r"((r)[13]), "=r"((r)[14]), "=r"((r)[15]), \
          "=r"((r)[16]), "=r"((r)[17]), "=r"((r)[18]), "=r"((r)[19]), \
          "=r"((r)[20]), "=r"((r)[21]), "=r"((r)[22]), "=r"((r)[23]), \
          "=r"((r)[24]), "=r"((r)[25]), "=r"((r)[26]), "=r"((r)[27]), \
          "=r"((r)[28]), "=r"((r)[29]), "=r"((r)[30]), "=r"((r)[31]) \
        : "r"(addr))

static constexpr uint64_t SMEM_DESC_BASE_SW128 =
    (uint64_t(2) << 61) | (uint64_t(1) << 46) | (uint64_t(64) << 32) | (uint64_t(1) << 16);
#define MAKE_SMEM_DESC(a) (SMEM_DESC_BASE_SW128 | ((uint64_t)((a) >> 4) & 0x3FFF))

__device__ __forceinline__ void mma_f16_ss(uint32_t d, uint64_t ad, uint64_t bd,
                                           uint32_t idesc, bool en) {
    uint32_t e = en ? 1u : 0u;
    asm volatile(
        "{\n\t.reg .pred p;\n\tsetp.ne.u32 p, %4, 0;\n\t"
        "tcgen05.mma.cta_group::1.kind::f16 [%0], %1, %2, %3, p;\n\t}"
        :: "r"(d), "l"(ad), "l"(bd), "r"(idesc), "r"(e) : "memory");
}

// idesc: F32 accum (1<<4), BF16 a/b (1<<7 | 1<<10), N>>3 <<17, M>>4 <<24
#define IDESC1 0x8400490u  /* M=128, N=256 */
#define IDESC2 0x8200490u  /* M=128, N=128 */
#endif  // USE_TC

// SMEM layout (bytes) for tcgen05 path
#define SM_A_HI 0
#define SM_A_LO 65536
#define SM_B_HI 131072
#define SM_B_LO 163840
#define SM_MISC 196608
#define EDGE_SMEM_BYTES (196608 + 4112)

// ---------------- small utility kernels ----------------------------------------
__global__ void zero_agg_kernel() {
    int i = blockIdx.x * blockDim.x + threadIdx.x;
    if (i < N_NODES * D) g_agg[i] = 0.f;
}
__global__ void zero_out_kernel(float* __restrict__ out) {
    if (threadIdx.x < N_GRAPHS) out[threadIdx.x] = 0.f;
}
__global__ void d2_kernel(const float* __restrict__ pos, const float* __restrict__ shift,
                          const float* __restrict__ lat, const int* __restrict__ ei,
                          const int* __restrict__ batch) {
    int e = blockIdx.x * blockDim.x + threadIdx.x;
    if (e >= N_EDGES) return;
    int s = ei[e];
    int d = ei[N_EDGES + e];
    int g = batch[s];
    const float* L = lat + g * 9;
    float sx = shift[e * 3 + 0], sy = shift[e * 3 + 1], sz = shift[e * 3 + 2];
    float vx = pos[d * 3 + 0] - pos[s * 3 + 0] + sx * L[0] + sy * L[3] + sz * L[6];
    float vy = pos[d * 3 + 1] - pos[s * 3 + 1] + sx * L[1] + sy * L[4] + sz * L[7];
    float vz = pos[d * 3 + 2] - pos[s * 3 + 2] + sx * L[2] + sy * L[5] + sz * L[8];
    g_d2[e] = vx * vx + vy * vy + vz * vz;
}
__global__ void embed_kernel(const float* __restrict__ embed, const int* __restrict__ z) {
    int i = blockIdx.x * blockDim.x + threadIdx.x;
    if (i >= N_NODES * D) return;
    int n = i >> 7, c = i & 127;
    g_x[i] = embed[z[n] * D + c];
}

// ---------------- weight conversion to bf16 hi/lo SMEM-image order -------------
__global__ void convert_w1(const float* __restrict__ ew1) {
    int i = blockIdx.x * blockDim.x + threadIdx.x;
    if (i >= 3 * 65536) return;
    int l = i >> 16, r = i & 65535, k = r >> 8, n = r & 255;
    float v = ew1[(size_t)l * 65792 + k * 256 + n];
    __nv_bfloat16 h = __float2bfloat16_rn(v);
    __nv_bfloat16 lo = __float2bfloat16_rn(v - __bfloat162float(h));
    uint32_t byte = ((uint32_t)(n >> 3) << 10) + ((n & 7) << 7) + ((k & 63) << 1);
    uint32_t sw = byte ^ ((byte >> 3) & 0x70);
    size_t idx = (size_t)l * 65536 + (size_t)(k >> 6) * 16384 + (sw >> 1);
    g_w1h[idx] = h; g_w1l[idx] = lo;
}
__global__ void convert_w2(const float* __restrict__ ew2) {
    int i = blockIdx.x * blockDim.x + threadIdx.x;
    if (i >= 3 * 32768) return;
    int l = i >> 15, r = i & 32767, k = r >> 7, n = r & 127;
    float v = ew2[(size_t)l * 32768 + k * 128 + n];
    __nv_bfloat16 h = __float2bfloat16_rn(v);
    __nv_bfloat16 lo = __float2bfloat16_rn(v - __bfloat162float(h));
    uint32_t byte = ((uint32_t)(n >> 3) << 10) + ((n & 7) << 7) + ((k & 63) << 1);
    uint32_t sw = byte ^ ((byte >> 3) & 0x70);
    size_t idx = (size_t)l * 32768 + (size_t)(k >> 6) * 8192 + (sw >> 1);
    g_w2h[idx] = h; g_w2l[idx] = lo;
}

// ---------------- fused edge MLP + scatter-add ---------------------------------
// 128 edges per CTA, 256 threads.
// USE_TC: bf16-split tcgen05 MMA (Ah*Bh + Ah*Bl + Al*Bh), fp32 TMEM accum.
// else:   proven fp32 FFMA path (4 sub-tiles of 32 edges).
__global__ __launch_bounds__(256) void edge_kernel(
    const float* __restrict__ W1f,   // fp32 W1 layer base [257,256]
    const float* __restrict__ b1,    // [256]
    const float* __restrict__ W2f,   // fp32 W2 layer base [256,128]
    const float* __restrict__ b2,    // [128]
    const int* __restrict__ ei, int layer)
{
#if USE_TC
    const float* w1r = W1f + 65536;  // W1 row 256 (d2 row)
    extern __shared__ __align__(1024) char smem[];
    char* smc = smem;
    const uint32_t sb = smem_to_u32(smem);
    const int t = threadIdx.x;
    const int wid = t >> 5;
    const int lane = t & 31;
    const int e0 = blockIdx.x * 128;

    int* s_dst   = (int*)(smc + SM_MISC + 16);
    int* s_src   = (int*)(smc + SM_MISC + 528);
    float* s_d2  = (float*)(smc + SM_MISC + 1040);
    float* s_b1  = (float*)(smc + SM_MISC + 1552);
    float* s_w1r = (float*)(smc + SM_MISC + 2576);
    float* s_b2  = (float*)(smc + SM_MISC + 3600);
    const uint32_t tmslot = sb + SM_MISC;
    const uint32_t mbar   = sb + SM_MISC + 8;

    if (wid == 7) TCGEN05_ALLOC(tmslot, 512);

    if (t < 128) {
        s_src[t] = ei[e0 + t];
        s_dst[t] = ei[N_EDGES + e0 + t];
        s_d2[t]  = g_d2[e0 + t];
        s_b2[t]  = b2[t];
    }
    s_b1[t]  = b1[t];
    s_w1r[t] = w1r[t];
    if (t == 0) MBARRIER_INIT(mbar, 1);
    __syncthreads();

    uint32_t tmem;
    asm volatile("ld.shared.b32 %0, [%1];" : "=r"(tmem) : "r"(tmslot));
    const uint32_t tmD1 = tmem;
    const uint32_t tmD2 = tmem + 256;

    // ---- gather ein (cols 0..127 = x[dst], 128..255 = x[src]) into A hi/lo ----
    for (int i = t; i < 128 * 64; i += 256) {
        const int m = i >> 6, q = i & 63;
        const float4* p = (q < 32)
            ? ((const float4*)(g_x + (size_t)s_dst[m] * D) + q)
            : ((const float4*)(g_x + (size_t)s_src[m] * D) + (q - 32));
        float4 v = *p;
        __nv_bfloat16 h0 = __float2bfloat16_rn(v.x), h1 = __float2bfloat16_rn(v.y);
        __nv_bfloat16 h2 = __float2bfloat16_rn(v.z), h3 = __float2bfloat16_rn(v.w);
        __nv_bfloat16 l0 = __float2bfloat16_rn(v.x - __bfloat162float(h0));
        __nv_bfloat16 l1 = __float2bfloat16_rn(v.y - __bfloat162float(h1));
        __nv_bfloat16 l2 = __float2bfloat16_rn(v.z - __bfloat162float(h2));
        __nv_bfloat16 l3 = __float2bfloat16_rn(v.w - __bfloat162float(h3));
        const int n0 = q * 4;
        uint32_t byte = ((uint32_t)((m >> 3) + ((n0 >> 6) << 4)) << 10)
                      + ((m & 7) << 7) + ((n0 & 63) << 1);
        uint32_t sw = byte ^ ((byte >> 3) & 0x70);
        uint2 hh; hh.x = packbf2(h0, h1); hh.y = packbf2(h2, h3);
        uint2 ll; ll.x = packbf2(l0, l1); ll.y = packbf2(l2, l3);
        *(uint2*)(smc + SM_A_HI + sw) = hh;
        *(uint2*)(smc + SM_A_LO + sw) = ll;
    }

    const uint64_t dAh = MAKE_SMEM_DESC(sb + SM_A_HI);
    const uint64_t dAl = MAKE_SMEM_DESC(sb + SM_A_LO);
    const uint64_t dBh = MAKE_SMEM_DESC(sb + SM_B_HI);
    const uint64_t dBl = MAKE_SMEM_DESC(sb + SM_B_LO);

    uint4* bH = (uint4*)(smc + SM_B_HI);
    uint4* bL = (uint4*)(smc + SM_B_LO);
    int ph = 0;

    // ---- GEMM1: D1[128,256] = ein @ W1 (K=256, 4 chunks of 64) ----
    for (int c = 0; c < 4; c++) {
        const uint4* wh = (const uint4*)g_w1h + ((size_t)layer * 65536 + (size_t)c * 16384) / 8;
        const uint4* wl = (const uint4*)g_w1l + ((size_t)layer * 65536 + (size_t)c * 16384) / 8;
        for (int i = t; i < 2048; i += 256) { bH[i] = wh[i]; bL[i] = wl[i]; }
        FENCE_ASYNC();
        __syncthreads();
        if (wid == 7) {
            if (elect_one_pred()) {
                #pragma unroll
                for (int kk = 0; kk < 4; kk++) {
                    const int s = c * 4 + kk;
                    const uint32_t aoff = (uint32_t)(s >> 2) * 1024 + (s & 3) * 2;
                    const uint32_t boff = kk * 2;
                    mma_f16_ss(tmD1, dAh + aoff, dBh + boff, IDESC1, !(c == 0 && kk == 0));
                    mma_f16_ss(tmD1, dAh + aoff, dBl + boff, IDESC1, true);
                    mma_f16_ss(tmD1, dAl + aoff, dBh + boff, IDESC1, true);
                }
                TCGEN05_COMMIT(mbar);
            }
        }
        MBARRIER_WAIT_PARITY(mbar, ph & 1); ph++;
    }
    TCGEN05_FENCE_AFTER();

    // ---- epilogue 1: m1 = swish(D1 + b1 + d2*w1r) -> A hi/lo (warps 0-3);
    //      warps 4-7 prefetch W2 chunk 0 ----
    if (wid < 4) {
        const int row = wid * 32 + lane;
        const float d2m = s_d2[row];
        #pragma unroll
        for (int cb = 0; cb < 8; cb++) {
            uint32_t r[32];
            TCGEN05_LD_X32(r, tmD1 + cb * 32);
            TCGEN05_WAIT_LD();
            #pragma unroll
            for (int j = 0; j < 32; j += 2) {
                const int n = cb * 32 + j;
                float v0 = swishf(__uint_as_float(r[j])     + s_b1[n]     + d2m * s_w1r[n]);
                float v1 = swishf(__uint_as_float(r[j + 1]) + s_b1[n + 1] + d2m * s_w1r[n + 1]);
                __nv_bfloat16 h0 = __float2bfloat16_rn(v0), h1 = __float2bfloat16_rn(v1);
                __nv_bfloat16 l0 = __float2bfloat16_rn(v0 - __bfloat162float(h0));
                __nv_bfloat16 l1 = __float2bfloat16_rn(v1 - __bfloat162float(h1));
                uint32_t byte = ((uint32_t)((row >> 3) + ((n >> 6) << 4)) << 10)
                              + ((row & 7) << 7) + ((n & 63) << 1);
                uint32_t sw = byte ^ ((byte >> 3) & 0x70);
                *(uint32_t*)(smc + SM_A_HI + sw) = packbf2(h0, h1);
                *(uint32_t*)(smc + SM_A_LO + sw) = packbf2(l0, l1);
            }
        }
    } else {
        const uint4* wh = (const uint4*)g_w2h + ((size_t)layer * 32768) / 8;
        const uint4* wl = (const uint4*)g_w2l + ((size_t)layer * 32768) / 8;
        for (int i = t - 128; i < 1024; i += 128) { bH[i] = wh[i]; bL[i] = wl[i]; }
    }
    FENCE_ASYNC();
    __syncthreads();

    // ---- GEMM2: D2[128,128] = m1 @ W2 (K=256, 4 chunks) ----
    for (int c = 0; c < 4; c++) {
        if (c > 0) {
            const uint4* wh = (const uint4*)g_w2h + ((size_t)layer * 32768 + (size_t)c * 8192) / 8;
            const uint4* wl = (const uint4*)g_w2l + ((size_t)layer * 32768 + (size_t)c * 8192) / 8;
            for (int i = t; i < 1024; i += 256) { bH[i] = wh[i]; bL[i] = wl[i]; }
            FENCE_ASYNC();
        }
        __syncthreads();
        if (wid == 7) {
            if (elect_one_pred()) {
                #pragma unroll
                for (int kk = 0; kk < 4; kk++) {
                    const int s = c * 4 + kk;
                    const uint32_t aoff = (uint32_t)(s >> 2) * 1024 + (s & 3) * 2;
                    const uint32_t boff = kk * 2;
                    mma_f16_ss(tmD2, dAh + aoff, dBh + boff, IDESC2, !(c == 0 && kk == 0));
                    mma_f16_ss(tmD2, dAh + aoff, dBl + boff, IDESC2, true);
                    mma_f16_ss(tmD2, dAl + aoff, dBh + boff, IDESC2, true);
                }
                TCGEN05_COMMIT(mbar);
            }
        }
        MBARRIER_WAIT_PARITY(mbar, ph & 1); ph++;
    }
    TCGEN05_FENCE_AFTER();

    // ---- epilogue 2: m2 = swish(D2 + b2) -> atomic scatter to agg[dst] ----
    if (wid < 4) {
        const int row = wid * 32 + lane;
        float* arow = g_agg + (size_t)s_dst[row] * D;
        #pragma unroll
        for (int cb = 0; cb < 4; cb++) {
            uint32_t r[32];
            TCGEN05_LD_X32(r, tmD2 + cb * 32);
            TCGEN05_WAIT_LD();
            #pragma unroll
            for (int j = 0; j < 32; j += 4) {
                const int n = cb * 32 + j;
                float v0 = swishf(__uint_as_float(r[j])     + s_b2[n]);
                float v1 = swishf(__uint_as_float(r[j + 1]) + s_b2[n + 1]);
                float v2 = swishf(__uint_as_float(r[j + 2]) + s_b2[n + 2]);
                float v3 = swishf(__uint_as_float(r[j + 3]) + s_b2[n + 3]);
                asm volatile("red.global.add.v4.f32 [%0], {%1, %2, %3, %4};"
                             :: "l"(arow + n), "f"(v0), "f"(v1), "f"(v2), "f"(v3)
                             : "memory");
            }
        }
    }

    __syncthreads();
    if (t == 0) MBARRIER_INVAL(mbar);
    __syncthreads();
    if (wid == 7) {
        TCGEN05_RELINQ();
        TCGEN05_DEALLOC(tmem, 512);
    }

#else  // ---------------- fp32 FFMA fallback (proven R2 path, 4x 32-edge subs) ----
    extern __shared__ float sm[];
    float* s_in = sm;                       // [32][256]
    float* s_w  = sm + 8192;                // weight staging
    float* s_d2 = sm + 16384;               // [32]
    int*   s_src = (int*)(sm + 16384 + 32); // [32]
    int*   s_dst = s_src + 32;              // [32]

    const int t  = threadIdx.x;
    const int eg = t >> 5;
    const int cg = t & 31;
    (void)layer;

    for (int sub = 0; sub < 4; sub++) {
        const int e0 = blockIdx.x * 128 + sub * 32;
        __syncthreads();
        if (t < 32) {
            s_src[t] = ei[e0 + t];
            s_dst[t] = ei[N_EDGES + e0 + t];
            s_d2[t]  = g_d2[e0 + t];
        }
        __syncthreads();

        for (int i = t; i < 32 * 64; i += 256) {
            const int e = i >> 6, q = i & 63;
            const float4* p = (q < 32)
                ? ((const float4*)(g_x + (size_t)s_dst[e] * D) + q)
                : ((const float4*)(g_x + (size_t)s_src[e] * D) + (q - 32));
            ((float4*)(s_in + e * 256))[q] = *p;
        }

        float acc[4][8];
        #pragma unroll
        for (int i = 0; i < 4; i++)
            #pragma unroll
            for (int j = 0; j < 8; j++) acc[i][j] = 0.f;

        for (int k0 = 0; k0 < 256; k0 += 32) {
            __syncthreads();
            #pragma unroll
            for (int i = t; i < 2048; i += 256)
                ((float4*)s_w)[i] = ((const float4*)W1f)[k0 * 64 + i];
            __syncthreads();
            #pragma unroll
            for (int kk4 = 0; kk4 < 32; kk4 += 4) {
                float xs[4][4];
                #pragma unroll
                for (int i = 0; i < 4; i++) {
                    float4 xv = *((const float4*)(s_in + (eg * 4 + i) * 256 + k0 + kk4));
                    xs[i][0] = xv.x; xs[i][1] = xv.y; xs[i][2] = xv.z; xs[i][3] = xv.w;
                }
                #pragma unroll
                for (int u = 0; u < 4; u++) {
                    const int kk = kk4 + u;
                    float4 w0 = *((const float4*)(s_w + kk * 256 + cg * 4));
                    float4 w1 = *((const float4*)(s_w + kk * 256 + 128 + cg * 4));
                    #pragma unroll
                    for (int i = 0; i < 4; i++) {
                        float xv = xs[i][u];
                        acc[i][0] = fmaf(xv, w0.x, acc[i][0]);
                        acc[i][1] = fmaf(xv, w0.y, acc[i][1]);
                        acc[i][2] = fmaf(xv, w0.z, acc[i][2]);
                        acc[i][3] = fmaf(xv, w0.w, acc[i][3]);
                        acc[i][4] = fmaf(xv, w1.x, acc[i][4]);
                        acc[i][5] = fmaf(xv, w1.y, acc[i][5]);
                        acc[i][6] = fmaf(xv, w1.z, acc[i][6]);
                        acc[i][7] = fmaf(xv, w1.w, acc[i][7]);
                    }
                }
            }
        }

        float4 wd0 = *((const float4*)(W1f + 256 * 256 + cg * 4));
        float4 wd1 = *((const float4*)(W1f + 256 * 256 + 128 + cg * 4));
        float4 bb0 = *((const float4*)(b1 + cg * 4));
        float4 bb1 = *((const float4*)(b1 + 128 + cg * 4));

        __syncthreads();
        #pragma unroll
        for (int i = 0; i < 4; i++) {
            float dv = s_d2[eg * 4 + i];
            float4 r0, r1;
            r0.x = swishf(fmaf(dv, wd0.x, acc[i][0]) + bb0.x);
            r0.y = swishf(fmaf(dv, wd0.y, acc[i][1]) + bb0.y);
            r0.z = swishf(fmaf(dv, wd0.z, acc[i][2]) + bb0.z);
            r0.w = swishf(fmaf(dv, wd0.w, acc[i][3]) + bb0.w);
            r1.x = swishf(fmaf(dv, wd1.x, acc[i][4]) + bb1.x);
            r1.y = swishf(fmaf(dv, wd1.y, acc[i][5]) + bb1.y);
            r1.z = swishf(fmaf(dv, wd1.z, acc[i][6]) + bb1.z);
            r1.w = swishf(fmaf(dv, wd1.w, acc[i][7]) + bb1.w);
            *((float4*)(s_in + (eg * 4 + i) * 256 + cg * 4)) = r0;
            *((float4*)(s_in + (eg * 4 + i) * 256 + 128 + cg * 4)) = r1;
        }

        float a2[4][4];
        #pragma unroll
        for (int i = 0; i < 4; i++)
            #pragma unroll
            for (int j = 0; j < 4; j++) a2[i][j] = 0.f;

        for (int k0 = 0; k0 < 256; k0 += 32) {
            __syncthreads();
            #pragma unroll
            for (int i = t; i < 1024; i += 256)
                ((float4*)s_w)[i] = ((const float4*)W2f)[k0 * 32 + i];
            __syncthreads();
            #pragma unroll
            for (int kk4 = 0; kk4 < 32; kk4 += 4) {
                float xs[4][4];
                #pragma unroll
                for (int i = 0; i < 4; i++) {
                    float4 xv = *((const float4*)(s_in + (eg * 4 + i) * 256 + k0 + kk4));
                    xs[i][0] = xv.x; xs[i][1] = xv.y; xs[i][2] = xv.z; xs[i][3] = xv.w;
                }
                #pragma unroll
                for (int u = 0; u < 4; u++) {
                    const int kk = kk4 + u;
                    float4 wv = *((const float4*)(s_w + kk * 128 + cg * 4));
                    #pragma unroll
                    for (int i = 0; i < 4; i++) {
                        float xv = xs[i][u];
                        a2[i][0] = fmaf(xv, wv.x, a2[i][0]);
                        a2[i][1] = fmaf(xv, wv.y, a2[i][1]);
                        a2[i][2] = fmaf(xv, wv.z, a2[i][2]);
                        a2[i][3] = fmaf(xv, wv.w, a2[i][3]);
                    }
                }
            }
        }

        float4 bb = *((const float4*)(b2 + cg * 4));
        #pragma unroll
        for (int i = 0; i < 4; i++) {
            float* ap = g_agg + (size_t)s_dst[eg * 4 + i] * D + cg * 4;
            atomicAdd(ap + 0, swishf(a2[i][0] + bb.x));
            atomicAdd(ap + 1, swishf(a2[i][1] + bb.y));
            atomicAdd(ap + 2, swishf(a2[i][2] + bb.z));
            atomicAdd(ap + 3, swishf(a2[i][3] + bb.w));
        }
    }
#endif
}

// ---------------- fp32 node MLP (residual) -------------------------------------
__global__ __launch_bounds__(256) void node_kernel(
    const float* __restrict__ W1, const float* __restrict__ b1,
    const float* __restrict__ W2, const float* __restrict__ b2)
{
    extern __shared__ float sm[];
    float* s_in = sm;
    float* s_w  = sm + 8192;

    const int t  = threadIdx.x;
    const int n0 = blockIdx.x * 32;

    #pragma unroll
    for (int i = t; i < 32 * 64; i += 256) {
        const int r = i >> 6, q = i & 63;
        int n = n0 + r; if (n >= N_NODES) n = N_NODES - 1;
        ((float4*)(s_in + r * 256))[q] = (q < 32)
            ? ((const float4*)(g_x + (size_t)n * D))[q]
            : ((const float4*)(g_agg + (size_t)n * D))[q - 32];
    }

    const int eg = t >> 5;
    const int cg = t & 31;

    float acc[4][8];
    #pragma unroll
    for (int i = 0; i < 4; i++)
        #pragma unroll
        for (int j = 0; j < 8; j++) acc[i][j] = 0.f;

    for (int k0 = 0; k0 < 256; k0 += 32) {
        __syncthreads();
        #pragma unroll
        for (int i = t; i < 2048; i += 256)
            ((float4*)s_w)[i] = ((const float4*)W1)[k0 * 64 + i];
        __syncthreads();
        #pragma unroll
        for (int kk4 = 0; kk4 < 32; kk4 += 4) {
            float xs[4][4];
            #pragma unroll
            for (int i = 0; i < 4; i++) {
                float4 xv = *((const float4*)(s_in + (eg * 4 + i) * 256 + k0 + kk4));
                xs[i][0] = xv.x; xs[i][1] = xv.y; xs[i][2] = xv.z; xs[i][3] = xv.w;
            }
            #pragma unroll
            for (int u = 0; u < 4; u++) {
                const int kk = kk4 + u;
                float4 w0 = *((const float4*)(s_w + kk * 256 + cg * 4));
                float4 w1 = *((const float4*)(s_w + kk * 256 + 128 + cg * 4));
                #pragma unroll
                for (int i = 0; i < 4; i++) {
                    float xv = xs[i][u];
                    acc[i][0] = fmaf(xv, w0.x, acc[i][0]);
                    acc[i][1] = fmaf(xv, w0.y, acc[i][1]);
                    acc[i][2] = fmaf(xv, w0.z, acc[i][2]);
                    acc[i][3] = fmaf(xv, w0.w, acc[i][3]);
                    acc[i][4] = fmaf(xv, w1.x, acc[i][4]);
                    acc[i][5] = fmaf(xv, w1.y, acc[i][5]);
                    acc[i][6] = fmaf(xv, w1.z, acc[i][6]);
                    acc[i][7] = fmaf(xv, w1.w, acc[i][7]);
                }
            }
        }
    }

    float4 bb0 = *((const float4*)(b1 + cg * 4));
    float4 bb1 = *((const float4*)(b1 + 128 + cg * 4));

    __syncthreads();
    #pragma unroll
    for (int i = 0; i < 4; i++) {
        float4 r0, r1;
        r0.x = swishf(acc[i][0] + bb0.x);
        r0.y = swishf(acc[i][1] + bb0.y);
        r0.z = swishf(acc[i][2] + bb0.z);
        r0.w = swishf(acc[i][3] + bb0.w);
        r1.x = swishf(acc[i][4] + bb1.x);
        r1.y = swishf(acc[i][5] + bb1.y);
        r1.z = swishf(acc[i][6] + bb1.z);
        r1.w = swishf(acc[i][7] + bb1.w);
        *((float4*)(s_in + (eg * 4 + i) * 256 + cg * 4)) = r0;
        *((float4*)(s_in + (eg * 4 + i) * 256 + 128 + cg * 4)) = r1;
    }

    float a2[4][4];
    #pragma unroll
    for (int i = 0; i < 4; i++)
        #pragma unroll
        for (int j = 0; j < 4; j++) a2[i][j] = 0.f;

    for (int k0 = 0; k0 < 256; k0 += 32) {
        __syncthreads();
        #pragma unroll
        for (int i = t; i < 1024; i += 256)
            ((float4*)s_w)[i] = ((const float4*)W2)[k0 * 32 + i];
        __syncthreads();
        #pragma unroll
        for (int kk4 = 0; kk4 < 32; kk4 += 4) {
            float xs[4][4];
            #pragma unroll
            for (int i = 0; i < 4; i++) {
                float4 xv = *((const float4*)(s_in + (eg * 4 + i) * 256 + k0 + kk4));
                xs[i][0] = xv.x; xs[i][1] = xv.y; xs[i][2] = xv.z; xs[i][3] = xv.w;
            }
            #pragma unroll
            for (int u = 0; u < 4; u++) {
                const int kk = kk4 + u;
                float4 wv = *((const float4*)(s_w + kk * 128 + cg * 4));
                #pragma unroll
                for (int i = 0; i < 4; i++) {
                    float xv = xs[i][u];
                    a2[i][0] = fmaf(xv, wv.x, a2[i][0]);
                    a2[i][1] = fmaf(xv, wv.y, a2[i][1]);
                    a2[i][2] = fmaf(xv, wv.z, a2[i][2]);
                    a2[i][3] = fmaf(xv, wv.w, a2[i][3]);
                }
            }
        }
    }

    float4 bb = *((const float4*)(b2 + cg * 4));
    #pragma unroll
    for (int i = 0; i < 4; i++) {
        int n = n0 + eg * 4 + i;
        if (n < N_NODES) {
            float4* xp = (float4*)(g_x + (size_t)n * D + cg * 4);
            float4 o = *xp;
            o.x += a2[i][0] + bb.x;
            o.y += a2[i][1] + bb.y;
            o.z += a2[i][2] + bb.z;
            o.w += a2[i][3] + bb.w;
            *xp = o;
        }
    }
}

// ---------------- output head + graph pooling ----------------------------------
__global__ __launch_bounds__(256) void out_kernel(
    const float* __restrict__ W1, const float* __restrict__ b1,
    const float* __restrict__ w2, const float* __restrict__ b2,
    const int* __restrict__ batch, float* __restrict__ out)
{
    extern __shared__ float sm[];
    float* s_in = sm;
    float* s_w  = sm + 4096;

    const int t  = threadIdx.x;
    const int n0 = blockIdx.x * 32;

    #pragma unroll
    for (int i = t; i < 1024; i += 256) {
        const int r = i >> 5, q = i & 31;
        int n = n0 + r; if (n >= N_NODES) n = N_NODES - 1;
        ((float4*)(s_in + r * 128))[q] = ((const float4*)(g_x + (size_t)n * D))[q];
    }

    const int eg = t >> 5;
    const int cg = t & 31;

    float acc[4][8];
    #pragma unroll
    for (int i = 0; i < 4; i++)
        #pragma unroll
        for (int j = 0; j < 8; j++) acc[i][j] = 0.f;

    for (int k0 = 0; k0 < 128; k0 += 32) {
        __syncthreads();
        #pragma unroll
        for (int i = t; i < 2048; i += 256)
            ((float4*)s_w)[i] = ((const float4*)W1)[k0 * 64 + i];
        __syncthreads();
        #pragma unroll
        for (int kk4 = 0; kk4 < 32; kk4 += 4) {
            float xs[4][4];
            #pragma unroll
            for (int i = 0; i < 4; i++) {
                float4 xv = *((const float4*)(s_in + (eg * 4 + i) * 128 + k0 + kk4));
                xs[i][0] = xv.x; xs[i][1] = xv.y; xs[i][2] = xv.z; xs[i][3] = xv.w;
            }
            #pragma unroll
            for (int u = 0; u < 4; u++) {
                const int kk = kk4 + u;
                float4 w0 = *((const float4*)(s_w + kk * 256 + cg * 4));
                float4 w1 = *((const float4*)(s_w + kk * 256 + 128 + cg * 4));
                #pragma unroll
                for (int i = 0; i < 4; i++) {
                    float xv = xs[i][u];
                    acc[i][0] = fmaf(xv, w0.x, acc[i][0]);
                    acc[i][1] = fmaf(xv, w0.y, acc[i][1]);
                    acc[i][2] = fmaf(xv, w0.z, acc[i][2]);
                    acc[i][3] = fmaf(xv, w0.w, acc[i][3]);
                    acc[i][4] = fmaf(xv, w1.x, acc[i][4]);
                    acc[i][5] = fmaf(xv, w1.y, acc[i][5]);
                    acc[i][6] = fmaf(xv, w1.z, acc[i][6]);
                    acc[i][7] = fmaf(xv, w1.w, acc[i][7]);
                }
            }
        }
    }

    float4 bb0 = *((const float4*)(b1 + cg * 4));
    float4 bb1 = *((const float4*)(b1 + 128 + cg * 4));
    float4 w2a = *((const float4*)(w2 + cg * 4));
    float4 w2b = *((const float4*)(w2 + 128 + cg * 4));

    float pv[4];
    #pragma unroll
    for (int i = 0; i < 4; i++) {
        float s = 0.f;
        s = fmaf(swishf(acc[i][0] + bb0.x), w2a.x, s);
        s = fmaf(swishf(acc[i][1] + bb0.y), w2a.y, s);
        s = fmaf(swishf(acc[i][2] + bb0.z), w2a.z, s);
        s = fmaf(swishf(acc[i][3] + bb0.w), w2a.w, s);
        s = fmaf(swishf(acc[i][4] + bb1.x), w2b.x, s);
        s = fmaf(swishf(acc[i][5] + bb1.y), w2b.y, s);
        s = fmaf(swishf(acc[i][6] + bb1.z), w2b.z, s);
        s = fmaf(swishf(acc[i][7] + bb1.w), w2b.w, s);
        pv[i] = s;
    }

    #pragma unroll
    for (int off = 16; off > 0; off >>= 1) {
        #pragma unroll
        for (int i = 0; i < 4; i++)
            pv[i] += __shfl_down_sync(0xffffffffu, pv[i], off);
    }

    if (cg == 0) {
        float bias = b2[0];
        #pragma unroll
        for (int i = 0; i < 4; i++) {
            int n = n0 + eg * 4 + i;
            if (n < N_NODES) atomicAdd(&out[batch[n]], pv[i] + bias);
        }
    }
}

// ---------------- host launcher ------------------------------------------------
extern "C" void kernel_launch(void* const* d_in, const int* in_sizes, int n_in,
                              void* d_out, int out_size) {
    const float *positions = 0, *edge_shift = 0, *lattice = 0, *embed = 0;
    const float *ew1 = 0, *eb1 = 0, *ew2 = 0, *eb2 = 0;
    const float *nw1 = 0, *nb1 = 0, *nw2 = 0, *nb2 = 0;
    const float *ow1 = 0, *ob1 = 0, *ow2 = 0, *ob2 = 0;
    const int *z = 0, *ei = 0, *batch = 0;

    for (int i = 0; i < n_in; i++) {
        int s = in_sizes[i];
        const void* p = d_in[i];
        switch (s) {
            case 150000:  positions  = (const float*)p; break;
            case 2400000: edge_shift = (const float*)p; break;
            case 288:     lattice    = (const float*)p; break;
            case 12800:   embed      = (const float*)p; break;
            case 197376:  ew1        = (const float*)p; break;
            case 196608:  nw1        = (const float*)p; break;
            case 32768:   ow1        = (const float*)p; break;
            case 768:     if (!eb1) eb1 = (const float*)p; else nb1 = (const float*)p; break;
            case 98304:   if (!ew2) ew2 = (const float*)p; else nw2 = (const float*)p; break;
            case 384:     if (!eb2) eb2 = (const float*)p; else nb2 = (const float*)p; break;
            case 256:     if (!ob1) ob1 = (const float*)p; else ow2 = (const float*)p; break;
            case 1:       ob2        = (const float*)p; break;
            case 1600000: ei         = (const int*)p; break;
            case 50000:   if (!z) z = (const int*)p; else batch = (const int*)p; break;
            default: break;
        }
    }

    const int NODE_SMEM = 16384 * 4;
    const int OUT_SMEM  = (4096 + 8192) * 4;
    cudaFuncSetAttribute(edge_kernel, cudaFuncAttributeMaxDynamicSharedMemorySize, EDGE_SMEM_BYTES);
    cudaFuncSetAttribute(node_kernel, cudaFuncAttributeMaxDynamicSharedMemorySize, NODE_SMEM);
    cudaFuncSetAttribute(out_kernel,  cudaFuncAttributeMaxDynamicSharedMemorySize, OUT_SMEM);

    float* out = (float*)d_out;

    zero_out_kernel<<<1, 32>>>(out);
    d2_kernel<<<(N_EDGES + 255) / 256, 256>>>(positions, edge_shift, lattice, ei, batch);
    embed_kernel<<<(N_NODES * D + 255) / 256, 256>>>(embed, z);
    convert_w1<<<(3 * 65536 + 255) / 256, 256>>>(ew1);
    convert_w2<<<(3 * 32768 + 255) / 256, 256>>>(ew2);

    for (int l = 0; l < 3; l++) {
        zero_agg_kernel<<<(N_NODES * D + 255) / 256, 256>>>();
        edge_kernel<<<N_EDGES / 128, 256, EDGE_SMEM_BYTES>>>(
            ew1 + (size_t)l * 65792, eb1 + (size_t)l * 256,
            ew2 + (size_t)l * 32768, eb2 + (size_t)l * 128, ei, l);
        node_kernel<<<(N_NODES + 31) / 32, 256, NODE_SMEM>>>(
            nw1 + (size_t)l * 256 * 256, nb1 + (size_t)l * 256,
            nw2 + (size_t)l * 256 * 128, nb2 + (size_t)l * 128);
    }

    out_kernel<<<(N_NODES + 31) / 32, 256, OUT_SMEM>>>(ow1, ob1, ow2, ob2, batch, out);
}

// round 6
// speedup vs baseline: 2.7206x; 1.6481x over previous
#include <cuda_runtime.h>
#include <cuda_bf16.h>
#include <stdint.h>

#define N_NODES 50000
#define N_EDGES 800000
#define N_GRAPHS 32
#define D 128
#define H 256

#if defined(__CUDA_ARCH__) && (defined(__CUDA_ARCH_FEAT_SM103_ALL) || defined(__CUDA_ARCH_FEAT_SM100_ALL) || defined(__CUDA_ARCH_FEAT_SM101_ALL))
#define USE_TC 1
#else
#define USE_TC 0
#endif

__device__ float g_x[N_NODES * D];
__device__ float g_agg[N_NODES * D];
__device__ float g_d2[N_EDGES];
__device__ __align__(128) __nv_bfloat16 g_w1h[3 * 65536];
__device__ __align__(128) __nv_bfloat16 g_w1l[3 * 65536];
__device__ __align__(128) __nv_bfloat16 g_w2h[3 * 32768];
__device__ __align__(128) __nv_bfloat16 g_w2l[3 * 32768];

__device__ __forceinline__ float swishf(float v) { return __fdividef(v, 1.f + __expf(-v)); }
__device__ __forceinline__ uint32_t packbf2(__nv_bfloat16 a, __nv_bfloat16 b) {
    __nv_bfloat162 t; t.x = a; t.y = b; return *reinterpret_cast<uint32_t*>(&t);
}
__device__ __forceinline__ uint32_t smem_to_u32(const void* p) {
    uint32_t a;
    asm("{ .reg .u64 t; cvta.to.shared.u64 t, %1; cvt.u32.u64 %0, t; }" : "=r"(a) : "l"(p));
    return a;
}

#if USE_TC
__device__ __forceinline__ uint32_t elect_one_pred() {
    uint32_t p;
    asm volatile("{\n\t.reg .pred q;\n\telect.sync _|q, 0xFFFFFFFF;\n\tselp.b32 %0, 1, 0, q;\n\t}" : "=r"(p));
    return p;
}
#define TCGEN05_ALLOC(a, n)   asm volatile("tcgen05.alloc.cta_group::1.sync.aligned.shared::cta.b32 [%0], %1;" :: "r"((uint32_t)(a)), "r"((uint32_t)(n)) : "memory")
#define TCGEN05_DEALLOC(t, n) asm volatile("tcgen05.dealloc.cta_group::1.sync.aligned.b32 %0, %1;" :: "r"(t), "r"((uint32_t)(n)))
#define TCGEN05_RELINQ()      asm volatile("tcgen05.relinquish_alloc_permit.cta_group::1.sync.aligned;")
#define TCGEN05_COMMIT(mb)    asm volatile("tcgen05.commit.cta_group::1.mbarrier::arrive::one.shared::cluster.b64 [%0];" :: "r"((uint32_t)(mb)) : "memory")
#define TCGEN05_WAIT_LD()     asm volatile("tcgen05.wait::ld.sync.aligned;" ::: "memory")
#define TCGEN05_FENCE_AFTER() asm volatile("tcgen05.fence::after_thread_sync;" ::: "memory")
#define FENCE_ASYNC()         asm volatile("fence.proxy.async.shared::cta;" ::: "memory")
#define MBARRIER_INIT(mb, c)  asm volatile("mbarrier.init.shared.b64 [%0], %1;" :: "r"((uint32_t)(mb)), "r"((uint32_t)(c)) : "memory")
#define MBARRIER_INVAL(mb)    asm volatile("mbarrier.inval.shared.b64 [%0];" :: "r"((uint32_t)(mb)) : "memory")
#define MBARRIER_WAIT_PARITY(mb, par) do { \
    uint32_t _m = (uint32_t)(mb); uint32_t _p = (uint32_t)(par); uint32_t _d; \
    asm volatile("{\n\t.reg .pred p;\n\tmbarrier.try_wait.parity.acquire.cta.shared::cta.b64 p, [%1], %2;\n\tselp.b32 %0, 1, 0, p;\n\t}" : "=r"(_d) : "r"(_m), "r"(_p) : "memory"); \
    if (!_d) { asm volatile("{\n\t.reg .pred P1;\n\tWL_%=:\n\tmbarrier.try_wait.parity.acquire.cta.shared::cta.b64 P1, [%0], %1, 0x989680;\n\t@P1 bra.uni WD_%=;\n\tbra.uni WL_%=;\n\tWD_%=:\n\t}" :: "r"(_m), "r"(_p) : "memory"); } } while (0)
#define TCGEN05_LD_X32(r, a) \
    asm volatile("tcgen05.ld.sync.aligned.32x32b.x32.b32 " \
        "{%0, %1, %2, %3, %4, %5, %6, %7, %8, %9, %10, %11, %12, %13, %14, %15, " \
        "%16, %17, %18, %19, %20, %21, %22, %23, %24, %25, %26, %27, %28, %29, %30, %31}, [%32];" \
        : "=r"((r)[0]), "=r"((r)[1]), "=r"((r)[2]), "=r"((r)[3]), "=r"((r)[4]), "=r"((r)[5]), "=r"((r)[6]), "=r"((r)[7]), \
          "=r"((r)[8]), "=r"((r)[9]), "=r"((r)[10]), "=r"((r)[11]), "=r"((r)[12]), "=r"((r)[13]), "=r"((r)[14]), "=r"((r)[15]), \
          "=r"((r)[16]), "=r"((r)[17]), "=r"((r)[18]), "=r"((r)[19]), "=r"((r)[20]), "=r"((r)[21]), "=r"((r)[22]), "=r"((r)[23]), \
          "=r"((r)[24]), "=r"((r)[25]), "=r"((r)[26]), "=r"((r)[27]), "=r"((r)[28]), "=r"((r)[29]), "=r"((r)[30]), "=r"((r)[31]) \
        : "r"(a))

static constexpr uint64_t DESC128 = (uint64_t(2) << 61) | (uint64_t(1) << 46) | (uint64_t(64) << 32) | (uint64_t(1) << 16);
static constexpr uint64_t DESC64  = (uint64_t(4) << 61) | (uint64_t(1) << 46) | (uint64_t(32) << 32) | (uint64_t(1) << 16);
#define MKD128(a) (DESC128 | ((uint64_t)((a) >> 4) & 0x3FFF))
#define MKD64(a)  (DESC64  | ((uint64_t)((a) >> 4) & 0x3FFF))

__device__ __forceinline__ void mma_f16_ss(uint32_t d, uint64_t ad, uint64_t bd, uint32_t idesc, bool en) {
    uint32_t e = en ? 1u : 0u;
    asm volatile("{\n\t.reg .pred p;\n\tsetp.ne.u32 p, %4, 0;\n\ttcgen05.mma.cta_group::1.kind::f16 [%0], %1, %2, %3, p;\n\t}"
                 :: "r"(d), "l"(ad), "l"(bd), "r"(idesc), "r"(e) : "memory");
}
#define IDESC1 0x8400490u
#define IDESC2 0x8200490u
#endif

// SMEM layout (TC path)
#define SM_A_HI 0
#define SM_A_LO 65536
#define SM_B    131072          /* 2 buffers x 32768 */
#define SM_TM   196608
#define SM_MB   196616          /* mb[0], mb[1] */
#define SM_DST  196640          /* int[128] */
#define SM_B1   197152          /* float[256] */
#define SM_W1R  198176          /* float[256] */
#define EDGE_SMEM_BYTES 199232

__device__ __forceinline__ void store_a_pair(char* smc, int row, int n, float v0, float v1) {
    __nv_bfloat16 h0 = __float2bfloat16_rn(v0), h1 = __float2bfloat16_rn(v1);
    __nv_bfloat16 l0 = __float2bfloat16_rn(v0 - __bfloat162float(h0));
    __nv_bfloat16 l1 = __float2bfloat16_rn(v1 - __bfloat162float(h1));
    uint32_t byte = ((uint32_t)((row >> 3) + ((n >> 6) << 4)) << 10) + ((row & 7) << 7) + ((n & 63) << 1);
    uint32_t sw = byte ^ ((byte >> 3) & 0x70);
    *(uint32_t*)(smc + SM_A_HI + sw) = packbf2(h0, h1);
    *(uint32_t*)(smc + SM_A_LO + sw) = packbf2(l0, l1);
}

// ---------------- prep (zero agg/out + embed + d2, ONE launch) ------------------
__global__ void prep_kernel(const float* __restrict__ pos, const float* __restrict__ shift,
                            const float* __restrict__ lat, const float* __restrict__ embed,
                            const int* __restrict__ ei, const int* __restrict__ batch,
                            const int* __restrict__ z, float* __restrict__ out) {
    int i = blockIdx.x * blockDim.x + threadIdx.x;
    if (i < N_NODES * D) {
        g_agg[i] = 0.f;
        g_x[i] = embed[z[i >> 7] * D + (i & 127)];
    }
    if (i < N_EDGES) {
        int s = ei[i], d = ei[N_EDGES + i];
        const float* L = lat + batch[s] * 9;
        float sx = shift[i * 3], sy = shift[i * 3 + 1], sz = shift[i * 3 + 2];
        float vx = pos[d * 3 + 0] - pos[s * 3 + 0] + sx * L[0] + sy * L[3] + sz * L[6];
        float vy = pos[d * 3 + 1] - pos[s * 3 + 1] + sx * L[1] + sy * L[4] + sz * L[7];
        float vz = pos[d * 3 + 2] - pos[s * 3 + 2] + sx * L[2] + sy * L[5] + sz * L[8];
        g_d2[i] = vx * vx + vy * vy + vz * vz;
    }
    if (i < N_GRAPHS) out[i] = 0.f;
}
__global__ void zero_agg_kernel() {
    int i = blockIdx.x * blockDim.x + threadIdx.x;
    if (i < N_NODES * D) g_agg[i] = 0.f;
}

// ---------------- weight conversion: 32-K SW64 images (16KB/8KB each) ----------
__global__ void convert_w1(const float* __restrict__ ew1) {
    int i = blockIdx.x * blockDim.x + threadIdx.x;
    if (i >= 3 * 65536) return;
    int l = i >> 16, r = i & 65535, k = r >> 8, n = r & 255;
    float v = ew1[(size_t)l * 65792 + k * 256 + n];
    __nv_bfloat16 h = __float2bfloat16_rn(v);
    __nv_bfloat16 lo = __float2bfloat16_rn(v - __bfloat162float(h));
    uint32_t byte = ((uint32_t)(n >> 3) << 9) + ((n & 7) << 6) + ((k & 31) << 1);
    uint32_t sw = byte ^ ((byte >> 3) & 0x30);
    size_t idx = (size_t)l * 65536 + (size_t)(k >> 5) * 8192 + (sw >> 1);
    g_w1h[idx] = h; g_w1l[idx] = lo;
}
__global__ void convert_w2(const float* __restrict__ ew2) {
    int i = blockIdx.x * blockDim.x + threadIdx.x;
    if (i >= 3 * 32768) return;
    int l = i >> 15, r = i & 32767, k = r >> 7, n = r & 127;
    float v = ew2[(size_t)l * 32768 + k * 128 + n];
    __nv_bfloat16 h = __float2bfloat16_rn(v);
    __nv_bfloat16 lo = __float2bfloat16_rn(v - __bfloat162float(h));
    uint32_t byte = ((uint32_t)(n >> 3) << 9) + ((n & 7) << 6) + ((k & 31) << 1);
    uint32_t sw = byte ^ ((byte >> 3) & 0x30);
    size_t idx = (size_t)l * 32768 + (size_t)(k >> 5) * 4096 + (sw >> 1);
    g_w2h[idx] = h; g_w2l[idx] = lo;
}

// ---------------- fused edge MLP + scatter (pipelined tcgen05) ------------------
__global__ __launch_bounds__(256) void edge_kernel(
    const float* __restrict__ W1f, const float* __restrict__ b1,
    const float* __restrict__ W2f, const float* __restrict__ b2,
    const int* __restrict__ ei, int layer)
{
#if USE_TC
    extern __shared__ __align__(1024) char smc[];
    const uint32_t sb = smem_to_u32(smc);
    const int t = threadIdx.x, wid = t >> 5, lane = t & 31;
    const int e0 = blockIdx.x * 128;
    const int half = wid >> 2;
    const int row = ((wid & 3) << 5) + lane;

    int*   s_dst = (int*)(smc + SM_DST);
    float* s_b1  = (float*)(smc + SM_B1);
    float* s_w1r = (float*)(smc + SM_W1R);
    const uint32_t mb0 = sb + SM_MB, mb1 = sb + SM_MB + 8;

    if (wid == 7) TCGEN05_ALLOC(sb + SM_TM, 512);
    if (t == 0) { MBARRIER_INIT(mb0, 1); MBARRIER_INIT(mb1, 1); }
    if (t < 128) s_dst[t] = ei[N_EDGES + e0 + t];
    s_b1[t]  = b1[t];
    s_w1r[t] = W1f[65536 + t];
    __syncthreads();

    uint32_t tmem;
    asm volatile("ld.shared.b32 %0, [%1];" : "=r"(tmem) : "r"(sb + SM_TM));
    const uint32_t tmD1 = tmem, tmD2 = tmem + 256;
    const uint64_t dAh = MKD128(sb + SM_A_HI), dAl = MKD128(sb + SM_A_LO);

    // ---- gather ein -> A hi/lo (SW128 image, proven R4 code) ----
    for (int i = t; i < 8192; i += 256) {
        const int m = i >> 6, q = i & 63;
        const int idx = (q < 32) ? s_dst[m] : __ldg(&ei[e0 + m]);
        float4 v = *((const float4*)(g_x + (size_t)idx * D) + (q & 31));
        const int n0 = q * 4;
        store_a_pair(smc, m, n0, v.x, v.y);
        store_a_pair(smc, m, n0 + 2, v.z, v.w);
    }
    FENCE_ASYNC();
    __syncthreads();

    int u0 = 0, u1 = 0;
    // ---- GEMM1: 8 chunks of 32-K, double-buffered ----
    for (int c = 0; c < 8; c++) {
        const int b = c & 1;
        const uint32_t mb = b ? mb1 : mb0;
        int& ub = b ? u1 : u0;
        if (c >= 2) MBARRIER_WAIT_PARITY(mb, (ub - 1) & 1);
        {
            const uint4* wh = (const uint4*)(g_w1h + (size_t)layer * 65536 + c * 8192);
            const uint4* wl = (const uint4*)(g_w1l + (size_t)layer * 65536 + c * 8192);
            char* dst = smc + SM_B + b * 32768;
            #pragma unroll
            for (int i = t; i < 1024; i += 256) { ((uint4*)dst)[i] = wh[i]; ((uint4*)(dst + 16384))[i] = wl[i]; }
        }
        FENCE_ASYNC();
        __syncthreads();
        if (wid == 0 && elect_one_pred()) {
            const uint32_t ba = sb + SM_B + b * 32768;
            const uint64_t bh = MKD64(ba), bl = MKD64(ba + 16384);
            #pragma unroll
            for (int u = 0; u < 2; u++) {
                const int s = 2 * c + u;
                const uint32_t ao = (uint32_t)(s >> 2) * 1024 + (s & 3) * 2;
                const uint32_t bo = u * 2;
                mma_f16_ss(tmD1, dAh + ao, bh + bo, IDESC1, !(c == 0 && u == 0));
                mma_f16_ss(tmD1, dAh + ao, bl + bo, IDESC1, true);
                mma_f16_ss(tmD1, dAl + ao, bh + bo, IDESC1, true);
            }
            TCGEN05_COMMIT(mb);
        }
        ub++;
    }
    MBARRIER_WAIT_PARITY(mb1, (u1 - 1) & 1);   // last commit covers ALL G1 MMAs
    TCGEN05_FENCE_AFTER();

    // ---- warps 4-7: prefetch G2 chunks 0,1 while warps 0-3 start ep1 ----
    if (half == 1) {
        const int pt = t - 128;
        const uint4* wh = (const uint4*)(g_w2h + (size_t)layer * 32768);
        const uint4* wl = (const uint4*)(g_w2l + (size_t)layer * 32768);
        #pragma unroll
        for (int i = pt; i < 1024; i += 128) {   // chunk0 -> buf0 (i<512), chunk1 -> buf1
            const int cc = i >> 9, j = i & 511;
            char* dst = smc + SM_B + cc * 32768;
            ((uint4*)dst)[j] = wh[i]; ((uint4*)(dst + 8192))[j] = wl[i];
        }
        FENCE_ASYNC();
    }
    // ---- ep1: m1 = swish(D1 + b1 + d2*w1r) -> A image (8 warps, col split) ----
    {
        const float d2m = __ldg(&g_d2[e0 + row]);
        #pragma unroll
        for (int i = 0; i < 4; i++) {
            const int cb = half * 4 + i;
            uint32_t r[32];
            TCGEN05_LD_X32(r, tmD1 + cb * 32);
            TCGEN05_WAIT_LD();
            #pragma unroll
            for (int j = 0; j < 32; j += 2) {
                const int n = cb * 32 + j;
                float v0 = swishf(__uint_as_float(r[j])     + s_b1[n]     + d2m * s_w1r[n]);
                float v1 = swishf(__uint_as_float(r[j + 1]) + s_b1[n + 1] + d2m * s_w1r[n + 1]);
                store_a_pair(smc, row, n, v0, v1);
            }
        }
    }
    FENCE_ASYNC();
    __syncthreads();

    // ---- GEMM2: 8 chunks (0,1 prefetched), double-buffered ----
    for (int c = 0; c < 8; c++) {
        const int b = c & 1;
        const uint32_t mb = b ? mb1 : mb0;
        int& ub = b ? u1 : u0;
        if (c >= 2) {
            MBARRIER_WAIT_PARITY(mb, (ub - 1) & 1);
            const uint4* wh = (const uint4*)(g_w2h + (size_t)layer * 32768 + c * 4096);
            const uint4* wl = (const uint4*)(g_w2l + (size_t)layer * 32768 + c * 4096);
            char* dst = smc + SM_B + b * 32768;
            #pragma unroll
            for (int i = t; i < 512; i += 256) { ((uint4*)dst)[i] = wh[i]; ((uint4*)(dst + 8192))[i] = wl[i]; }
            FENCE_ASYNC();
            __syncthreads();
        }
        if (wid == 0 && elect_one_pred()) {
            const uint32_t ba = sb + SM_B + b * 32768;
            const uint64_t bh = MKD64(ba), bl = MKD64(ba + 8192);
            #pragma unroll
            for (int u = 0; u < 2; u++) {
                const int s = 2 * c + u;
                const uint32_t ao = (uint32_t)(s >> 2) * 1024 + (s & 3) * 2;
                const uint32_t bo = u * 2;
                mma_f16_ss(tmD2, dAh + ao, bh + bo, IDESC2, !(c == 0 && u == 0));
                mma_f16_ss(tmD2, dAh + ao, bl + bo, IDESC2, true);
                mma_f16_ss(tmD2, dAl + ao, bh + bo, IDESC2, true);
            }
            TCGEN05_COMMIT(mb);
        }
        ub++;
    }
    MBARRIER_WAIT_PARITY(mb1, (u1 - 1) & 1);
    TCGEN05_FENCE_AFTER();

    // ---- ep2: swish(D2 + b2) -> scatter-add (8 warps, col split) ----
    {
        float* arow = g_agg + (size_t)s_dst[row] * D;
        #pragma unroll
        for (int i = 0; i < 2; i++) {
            const int cb = half * 2 + i;
            uint32_t r[32];
            TCGEN05_LD_X32(r, tmD2 + cb * 32);
            TCGEN05_WAIT_LD();
            #pragma unroll
            for (int j = 0; j < 32; j += 4) {
                const int n = cb * 32 + j;
                float v0 = swishf(__uint_as_float(r[j])     + __ldg(&b2[n]));
                float v1 = swishf(__uint_as_float(r[j + 1]) + __ldg(&b2[n + 1]));
                float v2 = swishf(__uint_as_float(r[j + 2]) + __ldg(&b2[n + 2]));
                float v3 = swishf(__uint_as_float(r[j + 3]) + __ldg(&b2[n + 3]));
                asm volatile("red.global.add.v4.f32 [%0], {%1, %2, %3, %4};"
                             :: "l"(arow + n), "f"(v0), "f"(v1), "f"(v2), "f"(v3) : "memory");
            }
        }
    }
    __syncthreads();
    if (t == 0) { MBARRIER_INVAL(mb0); MBARRIER_INVAL(mb1); }
    __syncthreads();
    if (wid == 7) { TCGEN05_RELINQ(); TCGEN05_DEALLOC(tmem, 512); }

#else
    // Minimal correct fallback (never selected at runtime on GB300 — sm_103a cubin wins).
    extern __shared__ float sm[];
    float* h1 = sm;           // [256]
    float* mm = sm + 256;     // [128]
    const int t = threadIdx.x;
    for (int e = blockIdx.x * 128; e < blockIdx.x * 128 + 128; e++) {
        int s = ei[e], d = ei[N_EDGES + e];
        float dv = g_d2[e];
        __syncthreads();
        if (t < H) {
            float acc = b1[t] + dv * W1f[256 * H + t];
            for (int k = 0; k < 128; k++) acc += g_x[(size_t)d * D + k] * W1f[k * H + t];
            for (int k = 0; k < 128; k++) acc += g_x[(size_t)s * D + k] * W1f[(128 + k) * H + t];
            h1[t] = swishf(acc);
        }
        __syncthreads();
        if (t < D) {
            float acc = b2[t];
            for (int k = 0; k < H; k++) acc += h1[k] * W2f[k * D + t];
            atomicAdd(&g_agg[(size_t)d * D + t], swishf(acc));
        }
    }
    (void)layer;
#endif
}

// ---------------- fp32 node MLP (proven) ---------------------------------------
__global__ __launch_bounds__(256) void node_kernel(
    const float* __restrict__ W1, const float* __restrict__ b1,
    const float* __restrict__ W2, const float* __restrict__ b2)
{
    extern __shared__ float sm[];
    float* s_in = sm;
    float* s_w  = sm + 8192;
    const int t = threadIdx.x, n0 = blockIdx.x * 32;
    const int eg = t >> 5, cg = t & 31;

    #pragma unroll
    for (int i = t; i < 2048; i += 256) {
        const int r = i >> 6, q = i & 63;
        int n = n0 + r; if (n >= N_NODES) n = N_NODES - 1;
        ((float4*)(s_in + r * 256))[q] = (q < 32)
            ? ((const float4*)(g_x + (size_t)n * D))[q]
            : ((const float4*)(g_agg + (size_t)n * D))[q - 32];
    }

    float acc[4][8];
    #pragma unroll
    for (int i = 0; i < 4; i++)
        #pragma unroll
        for (int j = 0; j < 8; j++) acc[i][j] = 0.f;

    for (int k0 = 0; k0 < 256; k0 += 32) {
        __syncthreads();
        #pragma unroll
        for (int i = t; i < 2048; i += 256) ((float4*)s_w)[i] = ((const float4*)W1)[k0 * 64 + i];
        __syncthreads();
        #pragma unroll
        for (int kk4 = 0; kk4 < 32; kk4 += 4) {
            float xs[4][4];
            #pragma unroll
            for (int i = 0; i < 4; i++) {
                float4 xv = *((const float4*)(s_in + (eg * 4 + i) * 256 + k0 + kk4));
                xs[i][0] = xv.x; xs[i][1] = xv.y; xs[i][2] = xv.z; xs[i][3] = xv.w;
            }
            #pragma unroll
            for (int u = 0; u < 4; u++) {
                float4 w0 = *((const float4*)(s_w + (kk4 + u) * 256 + cg * 4));
                float4 w1 = *((const float4*)(s_w + (kk4 + u) * 256 + 128 + cg * 4));
                #pragma unroll
                for (int i = 0; i < 4; i++) {
                    float xv = xs[i][u];
                    acc[i][0] = fmaf(xv, w0.x, acc[i][0]); acc[i][1] = fmaf(xv, w0.y, acc[i][1]);
                    acc[i][2] = fmaf(xv, w0.z, acc[i][2]); acc[i][3] = fmaf(xv, w0.w, acc[i][3]);
                    acc[i][4] = fmaf(xv, w1.x, acc[i][4]); acc[i][5] = fmaf(xv, w1.y, acc[i][5]);
                    acc[i][6] = fmaf(xv, w1.z, acc[i][6]); acc[i][7] = fmaf(xv, w1.w, acc[i][7]);
                }
            }
        }
    }

    float4 bb0 = *((const float4*)(b1 + cg * 4));
    float4 bb1 = *((const float4*)(b1 + 128 + cg * 4));
    __syncthreads();
    #pragma unroll
    for (int i = 0; i < 4; i++) {
        float4 r0, r1;
        r0.x = swishf(acc[i][0] + bb0.x); r0.y = swishf(acc[i][1] + bb0.y);
        r0.z = swishf(acc[i][2] + bb0.z); r0.w = swishf(acc[i][3] + bb0.w);
        r1.x = swishf(acc[i][4] + bb1.x); r1.y = swishf(acc[i][5] + bb1.y);
        r1.z = swishf(acc[i][6] + bb1.z); r1.w = swishf(acc[i][7] + bb1.w);
        *((float4*)(s_in + (eg * 4 + i) * 256 + cg * 4)) = r0;
        *((float4*)(s_in + (eg * 4 + i) * 256 + 128 + cg * 4)) = r1;
    }

    float a2[4][4];
    #pragma unroll
    for (int i = 0; i < 4; i++)
        #pragma unroll
        for (int j = 0; j < 4; j++) a2[i][j] = 0.f;

    for (int k0 = 0; k0 < 256; k0 += 32) {
        __syncthreads();
        #pragma unroll
        for (int i = t; i < 1024; i += 256) ((float4*)s_w)[i] = ((const float4*)W2)[k0 * 32 + i];
        __syncthreads();
        #pragma unroll
        for (int kk4 = 0; kk4 < 32; kk4 += 4) {
            float xs[4][4];
            #pragma unroll
            for (int i = 0; i < 4; i++) {
                float4 xv = *((const float4*)(s_in + (eg * 4 + i) * 256 + k0 + kk4));
                xs[i][0] = xv.x; xs[i][1] = xv.y; xs[i][2] = xv.z; xs[i][3] = xv.w;
            }
            #pragma unroll
            for (int u = 0; u < 4; u++) {
                float4 wv = *((const float4*)(s_w + (kk4 + u) * 128 + cg * 4));
                #pragma unroll
                for (int i = 0; i < 4; i++) {
                    float xv = xs[i][u];
                    a2[i][0] = fmaf(xv, wv.x, a2[i][0]); a2[i][1] = fmaf(xv, wv.y, a2[i][1]);
                    a2[i][2] = fmaf(xv, wv.z, a2[i][2]); a2[i][3] = fmaf(xv, wv.w, a2[i][3]);
                }
            }
        }
    }

    float4 bb = *((const float4*)(b2 + cg * 4));
    #pragma unroll
    for (int i = 0; i < 4; i++) {
        int n = n0 + eg * 4 + i;
        if (n < N_NODES) {
            float4* xp = (float4*)(g_x + (size_t)n * D + cg * 4);
            float4 o = *xp;
            o.x += a2[i][0] + bb.x; o.y += a2[i][1] + bb.y;
            o.z += a2[i][2] + bb.z; o.w += a2[i][3] + bb.w;
            *xp = o;
        }
    }
}

// ---------------- output head + pooling (proven) --------------------------------
__global__ __launch_bounds__(256) void out_kernel(
    const float* __restrict__ W1, const float* __restrict__ b1,
    const float* __restrict__ w2, const float* __restrict__ b2,
    const int* __restrict__ batch, float* __restrict__ out)
{
    extern __shared__ float sm[];
    float* s_in = sm;
    float* s_w  = sm + 4096;
    const int t = threadIdx.x, n0 = blockIdx.x * 32;
    const int eg = t >> 5, cg = t & 31;

    #pragma unroll
    for (int i = t; i < 1024; i += 256) {
        const int r = i >> 5, q = i & 31;
        int n = n0 + r; if (n >= N_NODES) n = N_NODES - 1;
        ((float4*)(s_in + r * 128))[q] = ((const float4*)(g_x + (size_t)n * D))[q];
    }

    float acc[4][8];
    #pragma unroll
    for (int i = 0; i < 4; i++)
        #pragma unroll
        for (int j = 0; j < 8; j++) acc[i][j] = 0.f;

    for (int k0 = 0; k0 < 128; k0 += 32) {
        __syncthreads();
        #pragma unroll
        for (int i = t; i < 2048; i += 256) ((float4*)s_w)[i] = ((const float4*)W1)[k0 * 64 + i];
        __syncthreads();
        #pragma unroll
        for (int kk4 = 0; kk4 < 32; kk4 += 4) {
            float xs[4][4];
            #pragma unroll
            for (int i = 0; i < 4; i++) {
                float4 xv = *((const float4*)(s_in + (eg * 4 + i) * 128 + k0 + kk4));
                xs[i][0] = xv.x; xs[i][1] = xv.y; xs[i][2] = xv.z; xs[i][3] = xv.w;
            }
            #pragma unroll
            for (int u = 0; u < 4; u++) {
                float4 w0 = *((const float4*)(s_w + (kk4 + u) * 256 + cg * 4));
                float4 w1 = *((const float4*)(s_w + (kk4 + u) * 256 + 128 + cg * 4));
                #pragma unroll
                for (int i = 0; i < 4; i++) {
                    float xv = xs[i][u];
                    acc[i][0] = fmaf(xv, w0.x, acc[i][0]); acc[i][1] = fmaf(xv, w0.y, acc[i][1]);
                    acc[i][2] = fmaf(xv, w0.z, acc[i][2]); acc[i][3] = fmaf(xv, w0.w, acc[i][3]);
                    acc[i][4] = fmaf(xv, w1.x, acc[i][4]); acc[i][5] = fmaf(xv, w1.y, acc[i][5]);
                    acc[i][6] = fmaf(xv, w1.z, acc[i][6]); acc[i][7] = fmaf(xv, w1.w, acc[i][7]);
                }
            }
        }
    }

    float4 bb0 = *((const float4*)(b1 + cg * 4));
    float4 bb1 = *((const float4*)(b1 + 128 + cg * 4));
    float4 w2a = *((const float4*)(w2 + cg * 4));
    float4 w2b = *((const float4*)(w2 + 128 + cg * 4));

    float pv[4];
    #pragma unroll
    for (int i = 0; i < 4; i++) {
        float s = 0.f;
        s = fmaf(swishf(acc[i][0] + bb0.x), w2a.x, s); s = fmaf(swishf(acc[i][1] + bb0.y), w2a.y, s);
        s = fmaf(swishf(acc[i][2] + bb0.z), w2a.z, s); s = fmaf(swishf(acc[i][3] + bb0.w), w2a.w, s);
        s = fmaf(swishf(acc[i][4] + bb1.x), w2b.x, s); s = fmaf(swishf(acc[i][5] + bb1.y), w2b.y, s);
        s = fmaf(swishf(acc[i][6] + bb1.z), w2b.z, s); s = fmaf(swishf(acc[i][7] + bb1.w), w2b.w, s);
        pv[i] = s;
    }
    #pragma unroll
    for (int off = 16; off > 0; off >>= 1)
        #pragma unroll
        for (int i = 0; i < 4; i++) pv[i] += __shfl_down_sync(0xffffffffu, pv[i], off);

    if (cg == 0) {
        float bias = b2[0];
        #pragma unroll
        for (int i = 0; i < 4; i++) {
            int n = n0 + eg * 4 + i;
            if (n < N_NODES) atomicAdd(&out[batch[n]], pv[i] + bias);
        }
    }
}

// ---------------- host launcher ------------------------------------------------
extern "C" void kernel_launch(void* const* d_in, const int* in_sizes, int n_in,
                              void* d_out, int out_size) {
    const float *positions = 0, *edge_shift = 0, *lattice = 0, *embed = 0;
    const float *ew1 = 0, *eb1 = 0, *ew2 = 0, *eb2 = 0;
    const float *nw1 = 0, *nb1 = 0, *nw2 = 0, *nb2 = 0;
    const float *ow1 = 0, *ob1 = 0, *ow2 = 0, *ob2 = 0;
    const int *z = 0, *ei = 0, *batch = 0;

    for (int i = 0; i < n_in; i++) {
        int s = in_sizes[i];
        const void* p = d_in[i];
        switch (s) {
            case 150000:  positions  = (const float*)p; break;
            case 2400000: edge_shift = (const float*)p; break;
            case 288:     lattice    = (const float*)p; break;
            case 12800:   embed      = (const float*)p; break;
            case 197376:  ew1        = (const float*)p; break;
            case 196608:  nw1        = (const float*)p; break;
            case 32768:   ow1        = (const float*)p; break;
            case 768:     if (!eb1) eb1 = (const float*)p; else nb1 = (const float*)p; break;
            case 98304:   if (!ew2) ew2 = (const float*)p; else nw2 = (const float*)p; break;
            case 384:     if (!eb2) eb2 = (const float*)p; else nb2 = (const float*)p; break;
            case 256:     if (!ob1) ob1 = (const float*)p; else ow2 = (const float*)p; break;
            case 1:       ob2        = (const float*)p; break;
            case 1600000: ei         = (const int*)p; break;
            case 50000:   if (!z) z = (const int*)p; else batch = (const int*)p; break;
            default: break;
        }
    }

    const int NODE_SMEM = 16384 * 4;
    const int OUT_SMEM  = (4096 + 8192) * 4;
    cudaFuncSetAttribute(edge_kernel, cudaFuncAttributeMaxDynamicSharedMemorySize, EDGE_SMEM_BYTES);
    cudaFuncSetAttribute(node_kernel, cudaFuncAttributeMaxDynamicSharedMemorySize, NODE_SMEM);
    cudaFuncSetAttribute(out_kernel,  cudaFuncAttributeMaxDynamicSharedMemorySize, OUT_SMEM);

    float* out = (float*)d_out;

    convert_w1<<<(3 * 65536 + 255) / 256, 256>>>(ew1);
    convert_w2<<<(3 * 32768 + 255) / 256, 256>>>(ew2);
    prep_kernel<<<(N_NODES * D + 255) / 256, 256>>>(positions, edge_shift, lattice, embed, ei, batch, z, out);

    for (int l = 0; l < 3; l++) {
        edge_kernel<<<N_EDGES / 128, 256, EDGE_SMEM_BYTES>>>(   // 4th launch for l==0 -> ncu
            ew1 + (size_t)l * 65792, eb1 + (size_t)l * 256,
            ew2 + (size_t)l * 32768, eb2 + (size_t)l * 128, ei, l);
        node_kernel<<<(N_NODES + 31) / 32, 256, NODE_SMEM>>>(
            nw1 + (size_t)l * 65536, nb1 + (size_t)l * 256,
            nw2 + (size_t)l * 32768, nb2 + (size_t)l * 128);
        if (l < 2) zero_agg_kernel<<<(N_NODES * D + 255) / 256, 256>>>();
    }

    out_kernel<<<(N_NODES + 31) / 32, 256, OUT_SMEM>>>(ow1, ob1, ow2, ob2, batch, out);
}